// round 11
// baseline (speedup 1.0000x reference)
#include <cuda_runtime.h>
#include <cuda_bf16.h>
#include <cstdint>
#include <math.h>

#define TOT   16384
#define NPTS  4096
#define KNN   16
#define HD    128
#define IND   64
#define AP    132    // A-buffer pitch (scalar frag loads: banks g*4+t unique)
#define WP    136    // W-buffer pitch (banks t*8+g unique)

// ---------------- device scratch ------------------------------------------------
__device__ int   g_idx[TOT * KNN];
__device__ float g_t  [TOT * HD];
__device__ float g_q  [TOT * HD];
__device__ float g_kf [TOT * HD];
__device__ float g_v  [TOT * HD];
__device__ float g_agg[TOT * HD];
__device__ float g_part[128 * 2 * HD];
__device__ float g_stats[2 * HD];
__device__ float g_wtf[6 * HD * HD];   // tf32 k-major: Wd2,Wg1,Wg2,Wphi,Wpsi,Walpha
__device__ unsigned int g_tick1;
__device__ unsigned int g_tick2;

__device__ __forceinline__ float to_tf32(float x) {
    unsigned int r;
    asm("cvt.rna.tf32.f32 %0, %1;" : "=r"(r) : "f"(x));
    return __uint_as_float(r);
}

__device__ __forceinline__ void cp16(void* dst_smem, const void* src) {
    unsigned int d = (unsigned int)__cvta_generic_to_shared(dst_smem);
    asm volatile("cp.async.cg.shared.global [%0], [%1], 16;\n" :: "r"(d), "l"(src));
}
__device__ __forceinline__ void cp_commit() {
    asm volatile("cp.async.commit_group;\n");
}
template <int N>
__device__ __forceinline__ void cp_wait() {
    asm volatile("cp.async.wait_group %0;\n" :: "n"(N));
}

// ============== weight pre-convert: 6 matrices -> tf32, k-major [k][c] ===========
__global__ __launch_bounds__(512) void conv_kernel(const float* __restrict__ Wd2,
                                                   const float* __restrict__ Wg1,
                                                   const float* __restrict__ Wg2,
                                                   const float* __restrict__ Wphi,
                                                   const float* __restrict__ Wpsi,
                                                   const float* __restrict__ Walpha) {
    int e = blockIdx.x * 512 + threadIdx.x;            // one float4 each
    const float* srcs[6] = {Wd2, Wg1, Wg2, Wphi, Wpsi, Walpha};
    int m = e / 4096, o = (e % 4096) * 4;
    if (m < 6) {
        float4 v = *(const float4*)&srcs[m][o];
        float4 w = {to_tf32(v.x), to_tf32(v.y), to_tf32(v.z), to_tf32(v.w)};
        *(float4*)&g_wtf[m * 16384 + o] = w;
    }
}

// ============================ ball query =========================================
__global__ __launch_bounds__(128) void ball_kernel(const int* __restrict__ coords) {
    __shared__ int sP[NPTS];
    int b = (blockIdx.x * 128) / NPTS;
    int base = b * NPTS;
    for (int j = threadIdx.x; j < NPTS; j += 128) {
        int4 c = *(const int4*)&coords[(size_t)(base + j) * 4];
        sP[j] = c.y | (c.z << 8) | (c.w << 16);
    }
    __syncthreads();
    int qi = blockIdx.x * 128 + threadIdx.x;
    int me = sP[qi - base];
    int qx = me & 255, qy = (me >> 8) & 255, qz = me >> 16;
    int cnt = 0, first = 0;
    int* out = g_idx + (size_t)qi * KNN;
    #pragma unroll 8
    for (int j = 0; j < NPTS; j++) {
        int p = sP[j];
        int dx = qx - (p & 255);
        int dy = qy - ((p >> 8) & 255);
        int dz = qz - (p >> 16);
        int d2 = dx * dx + dy * dy + dz * dz;
        if (d2 <= 100) {
            int gj = base + j;
            out[cnt] = gj;
            if (cnt == 0) first = gj;
            cnt++;
            if (cnt == KNN) break;
        }
    }
    for (int k = cnt; k < KNN; k++) out[k] = first;
}

// ================ t = x @ W_top + b_top, fused BN partials + finalize ===========
__global__ __launch_bounds__(256) void topproj_kernel(const float* __restrict__ x,
                                                      const float* __restrict__ W,
                                                      const float* __restrict__ bias) {
    __shared__ float As[16][128];
    __shared__ float Bs[16][128];
    __shared__ float redS[16][128];
    __shared__ float redSS[16][128];
    __shared__ double dS[2][128];
    __shared__ double dSS[2][128];
    __shared__ bool  sLast;
    int tid = threadIdx.x;
    int ty = tid >> 4, tx = tid & 15;
    int row0 = blockIdx.x * 128;
    float acc[8][8] = {};
    for (int kt = 0; kt < 64; kt += 16) {
        for (int e = tid; e < 512; e += 256) {
            int r = e >> 2, s = e & 3;
            float4 v = *(const float4*)&x[(size_t)(row0 + r) * 64 + kt + s * 4];
            As[s * 4 + 0][r] = v.x; As[s * 4 + 1][r] = v.y;
            As[s * 4 + 2][r] = v.z; As[s * 4 + 3][r] = v.w;
        }
        for (int e = tid; e < 512; e += 256) {
            int k = e >> 5, s = e & 31;
            *(float4*)&Bs[k][s * 4] = *(const float4*)&W[(size_t)(kt + k) * 128 + s * 4];
        }
        __syncthreads();
        #pragma unroll
        for (int k = 0; k < 16; k++) {
            float4 a0 = *(const float4*)&As[k][ty * 8];
            float4 a1 = *(const float4*)&As[k][ty * 8 + 4];
            float4 b0 = *(const float4*)&Bs[k][tx * 8];
            float4 b1 = *(const float4*)&Bs[k][tx * 8 + 4];
            float av[8] = {a0.x, a0.y, a0.z, a0.w, a1.x, a1.y, a1.z, a1.w};
            float bv[8] = {b0.x, b0.y, b0.z, b0.w, b1.x, b1.y, b1.z, b1.w};
            #pragma unroll
            for (int i = 0; i < 8; i++)
                #pragma unroll
                for (int j = 0; j < 8; j++)
                    acc[i][j] += av[i] * bv[j];
        }
        __syncthreads();
    }
    #pragma unroll
    for (int j = 0; j < 8; j++) {
        float b = __ldg(&bias[tx * 8 + j]);
        float s = 0.f, ss = 0.f;
        #pragma unroll
        for (int i = 0; i < 8; i++) {
            float v = acc[i][j] + b;
            g_t[(size_t)(row0 + ty * 8 + i) * 128 + tx * 8 + j] = v;
            s += v; ss += v * v;
        }
        redS[ty][tx * 8 + j] = s;
        redSS[ty][tx * 8 + j] = ss;
    }
    __syncthreads();
    if (tid < 128) {
        float s = 0.f, ss = 0.f;
        #pragma unroll
        for (int u = 0; u < 16; u++) { s += redS[u][tid]; ss += redSS[u][tid]; }
        g_part[blockIdx.x * 256 + tid]       = s;
        g_part[blockIdx.x * 256 + 128 + tid] = ss;
    }
    __threadfence();
    __syncthreads();
    if (tid == 0)
        sLast = (atomicAdd(&g_tick1, 1u) == gridDim.x - 1);
    __syncthreads();
    if (sLast) {
        int c = tid & 127, sub = tid >> 7;   // 2 subs x 128 channels
        double s = 0.0, ss = 0.0;
        for (int b = sub; b < 128; b += 2) {
            s  += (double)g_part[b * 256 + c];
            ss += (double)g_part[b * 256 + 128 + c];
        }
        dS[sub][c] = s; dSS[sub][c] = ss;
        __syncthreads();
        if (tid < 128) {
            double S = dS[0][tid] + dS[1][tid];
            double SS = dSS[0][tid] + dSS[1][tid];
            double m = S / (double)TOT;
            double var = SS / (double)TOT - m * m;
            g_stats[tid]       = (float)m;
            g_stats[128 + tid] = rsqrtf((float)var + 1e-5f);
        }
        if (tid == 0) g_tick1 = 0u;
    }
}

// ============================ tf32 mma GEMM core (MI=1) ==========================
// 128x128x128; 32 warps; warp tile 16x32 (wr=wid>>2 in 0..7, wc=wid&3); m16n8k8.
// A [128][AP] row-major tf32; W [128][WP] k-major tf32.
__device__ __forceinline__ void gemm_mma(const float* __restrict__ A,
                                         const float* __restrict__ W,
                                         float acc[4][4],
                                         int wr, int wc, int g, int t) {
    #pragma unroll
    for (int j = 0; j < 4; j++)
        #pragma unroll
        for (int r = 0; r < 4; r++) acc[j][r] = 0.f;
    #pragma unroll 4
    for (int kk = 0; kk < 16; kk++) {
        const int k0 = kk * 8;
        const float* ap = A + (size_t)(wr * 16 + g) * AP + k0 + t;
        unsigned int a0 = __float_as_uint(ap[0]);
        unsigned int a1 = __float_as_uint(ap[8 * AP]);
        unsigned int a2 = __float_as_uint(ap[4]);
        unsigned int a3 = __float_as_uint(ap[8 * AP + 4]);
        #pragma unroll
        for (int ni = 0; ni < 4; ni++) {
            const float* bp = W + (size_t)(k0 + t) * WP + wc * 32 + ni * 8 + g;
            unsigned int b0 = __float_as_uint(bp[0]);
            unsigned int b1 = __float_as_uint(bp[4 * WP]);
            asm volatile(
                "mma.sync.aligned.m16n8k8.row.col.f32.tf32.tf32.f32 "
                "{%0,%1,%2,%3}, {%4,%5,%6,%7}, {%8,%9}, {%0,%1,%2,%3};\n"
                : "+f"(acc[ni][0]), "+f"(acc[ni][1]),
                  "+f"(acc[ni][2]), "+f"(acc[ni][3])
                : "r"(a0), "r"(a1), "r"(a2), "r"(a3),
                  "r"(b0), "r"(b1));
        }
    }
}

// shared helper: async copy one 128x128 tf32 weight (k-major) into [128][WP] smem
__device__ __forceinline__ void ldW_async(float* dstBase, const float* src, int tid,
                                          int nthreads) {
    for (int e = tid; e < 4096; e += nthreads) {
        int r = e >> 5, c = (e & 31) * 4;
        cp16(dstBase + r * WP + c, src + r * 128 + c);
    }
}

// ============== q,kf,v = normalize(t) @ {W_phi,W_psi,W_alpha} (mma tf32) =========
__global__ __launch_bounds__(1024) void qkv_kernel(const float* __restrict__ g1v,
                                                   const float* __restrict__ be1) {
    extern __shared__ float sm[];
    float* BufA = sm;                    // [128][AP]
    float* W0   = BufA + 128 * AP;       // [128][WP]
    float* W1   = W0 + 128 * WP;         // [128][WP]
    __shared__ float sScale[128], sShift[128];
    int tid = threadIdx.x;

    // prefetch Wphi -> W0, Wpsi -> W1
    ldW_async(W0, g_wtf + 3 * 16384, tid, 1024);  cp_commit();
    ldW_async(W1, g_wtf + 4 * 16384, tid, 1024);  cp_commit();

    if (tid < 128) {
        float m = g_stats[tid], is = g_stats[128 + tid];
        float sc = is * g1v[tid];
        sScale[tid] = sc;
        sShift[tid] = be1[tid] - m * sc;
    }
    __syncthreads();
    int row0 = blockIdx.x * 128;
    for (int e = tid; e < 4096; e += 1024) {
        int r = e >> 5, s = (e & 31) * 4;
        float4 v = *(const float4*)&g_t[(size_t)(row0 + r) * 128 + s];
        float4 o;
        o.x = to_tf32(v.x * sScale[s] + sShift[s]);
        o.y = to_tf32(v.y * sScale[s + 1] + sShift[s + 1]);
        o.z = to_tf32(v.z * sScale[s + 2] + sShift[s + 2]);
        o.w = to_tf32(v.w * sScale[s + 3] + sShift[s + 3]);
        *(float4*)&BufA[r * AP + s] = o;
    }

    int wid = tid >> 5, lane = tid & 31;
    int wr = wid >> 2, wc = wid & 3;
    int g = lane >> 2, t = lane & 3;

    #pragma unroll 1
    for (int widx = 0; widx < 3; widx++) {
        float* out = (widx == 0) ? g_q : (widx == 1) ? g_kf : g_v;
        const float* Wb = (widx == 1) ? W1 : W0;
        if (widx < 2) { cp_wait<1>(); } else { cp_wait<0>(); }
        __syncthreads();

        float acc[4][4];
        gemm_mma(BufA, Wb, acc, wr, wc, g, t);
        __syncthreads();   // all reads of Wb done before any overwrite

        if (widx == 0) {   // prefetch Walpha -> W0 (free after GEMM0)
            ldW_async(W0, g_wtf + 5 * 16384, tid, 1024);
            cp_commit();
        }

        int r0 = row0 + wr * 16 + g;
        #pragma unroll
        for (int ni = 0; ni < 4; ni++) {
            int c0 = wc * 32 + ni * 8 + 2 * t;
            *(float2*)&out[(size_t)r0 * 128 + c0] =
                make_float2(acc[ni][0], acc[ni][1]);
            *(float2*)&out[(size_t)(r0 + 8) * 128 + c0] =
                make_float2(acc[ni][2], acc[ni][3]);
        }
    }
}

// ============================ fused per-point attention (mma tf32) ==============
// 8 points/block, 1024 threads, 32 warps, warp tile 16x32 (one point per warp).
// Weights double-buffered via cp.async; delta in regs; shuffle softmax.
__global__ __launch_bounds__(1024) void fused_kernel(const int* __restrict__ coords,
                                                     const float* __restrict__ Wd1,
                                                     const float* __restrict__ bd1,
                                                     const float* __restrict__ bd2,
                                                     const float* __restrict__ bg1,
                                                     const float* __restrict__ bg2) {
    extern __shared__ float sm[];
    float* BufA = sm;                      // [128][AP]
    float* W0   = BufA + 128 * AP;         // [128][WP]
    float* W1   = W0 + 128 * WP;           // [128][WP]
    float* sQ   = W1 + 128 * WP;           // [8][128]
    float* sRel = sQ + 8 * 128;            // [128][3]
    float* sWd1 = sRel + 128 * 3;          // [3][128]
    float* sBd1 = sWd1 + 384;              // [128]
    int*   sIdx = (int*)(sBd1 + 128);      // [128]

    int tid = threadIdx.x;
    int p0 = blockIdx.x * 8;
    int wid = tid >> 5, lane = tid & 31;
    int wr = wid >> 2, wc = wid & 3;
    int g = lane >> 2, t = lane & 3;

    // async weight loads: group1 = Wd2 -> W0, group2 = Wg1 -> W1
    ldW_async(W0, g_wtf, tid, 1024);           cp_commit();
    ldW_async(W1, g_wtf + 16384, tid, 1024);   cp_commit();

    if (tid < 128) {
        sIdx[tid] = g_idx[(size_t)p0 * KNN + tid];
        sBd1[tid] = bd1[tid];
    }
    if (tid < 384) sWd1[tid] = Wd1[tid];
    if (tid < 256) {
        int pp = tid >> 5, s = (tid & 31) * 4;
        *(float4*)&sQ[pp * 128 + s] = *(const float4*)&g_q[(size_t)(p0 + pp) * 128 + s];
    }
    __syncthreads();

    const int r0 = wr * 16 + g;      // row in [wr*16, wr*16+8)
    const int r1 = r0 + 8;           // row in [wr*16+8, wr*16+16)
    const int gi0 = sIdx[r0];
    const int gi1 = sIdx[r1];

    // prefetch kf gathers (consumed in epilogue1)
    float2 kf0[4], kf1[4];
    #pragma unroll
    for (int ni = 0; ni < 4; ni++) {
        int c0 = wc * 32 + ni * 8 + 2 * t;
        kf0[ni] = *(const float2*)&g_kf[(size_t)gi0 * 128 + c0];
        kf1[ni] = *(const float2*)&g_kf[(size_t)gi1 * 128 + c0];
    }

    if (tid < 128) {
        int i = p0 + (tid >> 4);
        int j = sIdx[tid];
        int4 ci = *(const int4*)&coords[(size_t)i * 4];
        int4 cj = *(const int4*)&coords[(size_t)j * 4];
        sRel[tid * 3 + 0] = (float)(ci.y - cj.y);
        sRel[tid * 3 + 1] = (float)(ci.z - cj.z);
        sRel[tid * 3 + 2] = (float)(ci.w - cj.w);
    }
    __syncthreads();

    // stage 1: BufA <- tf32(relu(rel @ Wd1 + bd1))
    for (int e = tid; e < 128 * 128; e += 1024) {
        int r = e >> 7, c = e & 127;
        float v = sBd1[c] + sRel[r * 3] * sWd1[c] + sRel[r * 3 + 1] * sWd1[128 + c]
                + sRel[r * 3 + 2] * sWd1[256 + c];
        BufA[r * AP + c] = to_tf32(fmaxf(v, 0.f));
    }
    cp_wait<1>();          // Wd2 resident
    __syncthreads();

    // GEMM1: delta = h1 @ Wd2 + bd2  (registers)
    float dlt[4][4];
    gemm_mma(BufA, W0, dlt, wr, wc, g, t);
    #pragma unroll
    for (int ni = 0; ni < 4; ni++) {
        int c0 = wc * 32 + ni * 8 + 2 * t;
        float b0 = __ldg(&bd2[c0]), b1 = __ldg(&bd2[c0 + 1]);
        dlt[ni][0] += b0; dlt[ni][1] += b1;
        dlt[ni][2] += b0; dlt[ni][3] += b1;
    }
    __syncthreads();       // all GEMM1 reads of BufA/W0 complete

    // group3: Wg2 -> W0 (W0 now free)
    ldW_async(W0, g_wtf + 32768, tid, 1024);
    cp_commit();

    // epilogue1: BufA <- tf32(q - kf + delta)   (point pl = wr)
    #pragma unroll
    for (int ni = 0; ni < 4; ni++) {
        int c0 = wc * 32 + ni * 8 + 2 * t;
        float q0 = sQ[wr * 128 + c0], q1 = sQ[wr * 128 + c0 + 1];
        *(float2*)&BufA[r0 * AP + c0] =
            make_float2(to_tf32(q0 - kf0[ni].x + dlt[ni][0]),
                        to_tf32(q1 - kf0[ni].y + dlt[ni][1]));
        *(float2*)&BufA[r1 * AP + c0] =
            make_float2(to_tf32(q0 - kf1[ni].x + dlt[ni][2]),
                        to_tf32(q1 - kf1[ni].y + dlt[ni][3]));
    }
    cp_wait<1>();          // Wg1 resident
    __syncthreads();

    // GEMM2: h2 = relu(apre @ Wg1 + bg1)
    float acc2[4][4];
    gemm_mma(BufA, W1, acc2, wr, wc, g, t);
    __syncthreads();       // GEMM2 reads of BufA complete
    #pragma unroll
    for (int ni = 0; ni < 4; ni++) {
        int c0 = wc * 32 + ni * 8 + 2 * t;
        float b0 = __ldg(&bg1[c0]), b1 = __ldg(&bg1[c0 + 1]);
        *(float2*)&BufA[r0 * AP + c0] =
            make_float2(to_tf32(fmaxf(acc2[ni][0] + b0, 0.f)),
                        to_tf32(fmaxf(acc2[ni][1] + b1, 0.f)));
        *(float2*)&BufA[r1 * AP + c0] =
            make_float2(to_tf32(fmaxf(acc2[ni][2] + b0, 0.f)),
                        to_tf32(fmaxf(acc2[ni][3] + b1, 0.f)));
    }
    cp_wait<0>();          // Wg2 resident
    __syncthreads();

    // GEMM3: logits = h2 @ Wg2 (+bg2 below)
    gemm_mma(BufA, W0, acc2, wr, wc, g, t);

    // softmax over K + aggregate (point wr), in registers/shuffles; v read here
    #pragma unroll
    for (int ni = 0; ni < 4; ni++) {
        int c0 = wc * 32 + ni * 8 + 2 * t;
        float b0 = __ldg(&bg2[c0]), b1 = __ldg(&bg2[c0 + 1]);
        float l00 = acc2[ni][0] + b0, l01 = acc2[ni][1] + b1;
        float l10 = acc2[ni][2] + b0, l11 = acc2[ni][3] + b1;
        float2 v0 = *(const float2*)&g_v[(size_t)gi0 * 128 + c0];
        float2 v1 = *(const float2*)&g_v[(size_t)gi1 * 128 + c0];
        float w00 = v0.x + dlt[ni][0], w01 = v0.y + dlt[ni][1];
        float w10 = v1.x + dlt[ni][2], w11 = v1.y + dlt[ni][3];

        float m0 = fmaxf(l00, l10);
        m0 = fmaxf(m0, __shfl_xor_sync(0xffffffffu, m0, 4));
        m0 = fmaxf(m0, __shfl_xor_sync(0xffffffffu, m0, 8));
        m0 = fmaxf(m0, __shfl_xor_sync(0xffffffffu, m0, 16));
        float m1 = fmaxf(l01, l11);
        m1 = fmaxf(m1, __shfl_xor_sync(0xffffffffu, m1, 4));
        m1 = fmaxf(m1, __shfl_xor_sync(0xffffffffu, m1, 8));
        m1 = fmaxf(m1, __shfl_xor_sync(0xffffffffu, m1, 16));

        float e00 = __expf(l00 - m0), e10 = __expf(l10 - m0);
        float e01 = __expf(l01 - m1), e11 = __expf(l11 - m1);
        float s0 = e00 + e10, s1 = e01 + e11;
        float a0 = e00 * w00 + e10 * w10;
        float a1 = e01 * w01 + e11 * w11;
        s0 += __shfl_xor_sync(0xffffffffu, s0, 4);
        s0 += __shfl_xor_sync(0xffffffffu, s0, 8);
        s0 += __shfl_xor_sync(0xffffffffu, s0, 16);
        s1 += __shfl_xor_sync(0xffffffffu, s1, 4);
        s1 += __shfl_xor_sync(0xffffffffu, s1, 8);
        s1 += __shfl_xor_sync(0xffffffffu, s1, 16);
        a0 += __shfl_xor_sync(0xffffffffu, a0, 4);
        a0 += __shfl_xor_sync(0xffffffffu, a0, 8);
        a0 += __shfl_xor_sync(0xffffffffu, a0, 16);
        a1 += __shfl_xor_sync(0xffffffffu, a1, 4);
        a1 += __shfl_xor_sync(0xffffffffu, a1, 8);
        a1 += __shfl_xor_sync(0xffffffffu, a1, 16);

        if (g == 0)
            *(float2*)&g_agg[(size_t)(p0 + wr) * 128 + c0] =
                make_float2(a0 / s0, a1 / s1);
    }
}

// ========== down-proj: out = agg @ W_down + b_down, fused BN partials ===========
__global__ __launch_bounds__(256) void down_kernel(const float* __restrict__ W,
                                                   const float* __restrict__ bias,
                                                   float* __restrict__ out) {
    __shared__ float As[16][128];
    __shared__ float Bs[16][64];
    __shared__ float redS[16][64];
    __shared__ float redSS[16][64];
    __shared__ double dS[4][64];
    __shared__ double dSS[4][64];
    __shared__ bool  sLast;
    int tid = threadIdx.x;
    int ty = tid >> 4, tx = tid & 15;
    int row0 = blockIdx.x * 128;
    float acc[8][4] = {};
    for (int kt = 0; kt < 128; kt += 16) {
        for (int e = tid; e < 512; e += 256) {
            int r = e >> 2, s = e & 3;
            float4 v = *(const float4*)&g_agg[(size_t)(row0 + r) * 128 + kt + s * 4];
            As[s * 4 + 0][r] = v.x; As[s * 4 + 1][r] = v.y;
            As[s * 4 + 2][r] = v.z; As[s * 4 + 3][r] = v.w;
        }
        if (tid < 256) {
            int k = tid >> 4, s = tid & 15;
            *(float4*)&Bs[k][s * 4] = *(const float4*)&W[(size_t)(kt + k) * 64 + s * 4];
        }
        __syncthreads();
        #pragma unroll
        for (int k = 0; k < 16; k++) {
            float4 a0 = *(const float4*)&As[k][ty * 8];
            float4 a1 = *(const float4*)&As[k][ty * 8 + 4];
            float4 b = *(const float4*)&Bs[k][tx * 4];
            float av[8] = {a0.x, a0.y, a0.z, a0.w, a1.x, a1.y, a1.z, a1.w};
            float bv[4] = {b.x, b.y, b.z, b.w};
            #pragma unroll
            for (int i = 0; i < 8; i++)
                #pragma unroll
                for (int j = 0; j < 4; j++)
                    acc[i][j] += av[i] * bv[j];
        }
        __syncthreads();
    }
    #pragma unroll
    for (int j = 0; j < 4; j++) {
        float b = __ldg(&bias[tx * 4 + j]);
        float s = 0.f, ss = 0.f;
        #pragma unroll
        for (int i = 0; i < 8; i++) {
            float v = acc[i][j] + b;
            out[(size_t)(row0 + ty * 8 + i) * 64 + tx * 4 + j] = v;
            s += v; ss += v * v;
        }
        redS[ty][tx * 4 + j] = s;
        redSS[ty][tx * 4 + j] = ss;
    }
    __syncthreads();
    if (tid < 64) {
        float s = 0.f, ss = 0.f;
        #pragma unroll
        for (int u = 0; u < 16; u++) { s += redS[u][tid]; ss += redSS[u][tid]; }
        g_part[blockIdx.x * 128 + tid]      = s;
        g_part[blockIdx.x * 128 + 64 + tid] = ss;
    }
    __threadfence();
    __syncthreads();
    if (tid == 0)
        sLast = (atomicAdd(&g_tick2, 1u) == gridDim.x - 1);
    __syncthreads();
    if (sLast) {
        int c = tid & 63, sub = tid >> 6;    // 4 subs x 64 channels
        double s = 0.0, ss = 0.0;
        for (int b = sub; b < 128; b += 4) {
            s  += (double)g_part[b * 128 + c];
            ss += (double)g_part[b * 128 + 64 + c];
        }
        dS[sub][c] = s; dSS[sub][c] = ss;
        __syncthreads();
        if (tid < 64) {
            double S = dS[0][tid] + dS[1][tid] + dS[2][tid] + dS[3][tid];
            double SS = dSS[0][tid] + dSS[1][tid] + dSS[2][tid] + dSS[3][tid];
            double m = S / (double)TOT;
            double var = SS / (double)TOT - m * m;
            g_stats[tid]      = (float)m;
            g_stats[64 + tid] = rsqrtf((float)var + 1e-5f);
        }
        if (tid == 0) g_tick2 = 0u;
    }
}

// ============================ final BN + residual ================================
__global__ __launch_bounds__(256) void final_kernel(const float* __restrict__ x,
                                                    const float* __restrict__ g2,
                                                    const float* __restrict__ be2,
                                                    float* __restrict__ out) {
    int e = blockIdx.x * 256 + threadIdx.x;
    if (e < TOT * IND) {
        int c = e & 63;
        float m = g_stats[c], is = g_stats[IND + c];
        out[e] = (out[e] - m) * is * g2[c] + be2[c] + x[e];
    }
}

// ============================ launch =============================================
extern "C" void kernel_launch(void* const* d_in, const int* in_sizes, int n_in,
                              void* d_out, int out_size) {
    const int*   coords  = (const int*)  d_in[0];
    const float* x       = (const float*)d_in[1];
    const float* W_top   = (const float*)d_in[2];
    const float* b_top   = (const float*)d_in[3];
    const float* g1      = (const float*)d_in[4];
    const float* be1     = (const float*)d_in[5];
    const float* W_phi   = (const float*)d_in[6];
    const float* W_psi   = (const float*)d_in[7];
    const float* W_alpha = (const float*)d_in[8];
    const float* Wd1     = (const float*)d_in[9];
    const float* bd1     = (const float*)d_in[10];
    const float* Wd2     = (const float*)d_in[11];
    const float* bd2     = (const float*)d_in[12];
    const float* Wg1     = (const float*)d_in[13];
    const float* bg1     = (const float*)d_in[14];
    const float* Wg2     = (const float*)d_in[15];
    const float* bg2     = (const float*)d_in[16];
    const float* W_down  = (const float*)d_in[17];
    const float* b_down  = (const float*)d_in[18];
    const float* g2      = (const float*)d_in[19];
    const float* be2     = (const float*)d_in[20];
    float* out = (float*)d_out;

    const size_t SMEM_F = (size_t)(128 * AP + 2 * 128 * WP + 8 * 128 + 128 * 3
                                   + 384 + 128 + 128) * 4;
    const size_t SMEM_Q = (size_t)(128 * AP + 2 * 128 * WP) * 4;
    cudaFuncSetAttribute(fused_kernel, cudaFuncAttributeMaxDynamicSharedMemorySize,
                         (int)SMEM_F);
    cudaFuncSetAttribute(qkv_kernel, cudaFuncAttributeMaxDynamicSharedMemorySize,
                         (int)SMEM_Q);

    conv_kernel<<<48, 512>>>(Wd2, Wg1, Wg2, W_phi, W_psi, W_alpha);
    ball_kernel<<<TOT / 128, 128>>>(coords);
    topproj_kernel<<<TOT / 128, 256>>>(x, W_top, b_top);
    qkv_kernel<<<TOT / 128, 1024, SMEM_Q>>>(g1, be1);
    fused_kernel<<<TOT / 8, 1024, SMEM_F>>>(coords, Wd1, bd1, bd2, bg1, bg2);
    down_kernel<<<TOT / 128, 256>>>(W_down, b_down, out);
    final_kernel<<<(TOT * IND + 255) / 256, 256>>>(x, g2, be2, out);
}

// round 12
// speedup vs baseline: 1.0658x; 1.0658x over previous
#include <cuda_runtime.h>
#include <cuda_bf16.h>
#include <cstdint>
#include <math.h>

#define TOT   16384
#define NPTS  4096
#define KNN   16
#define HD    128
#define IND   64
#define AP    132    // A-buffer pitch (scalar frag loads: banks g*4+t unique)
#define WP    136    // W-buffer pitch ([c][k'] layout; LDS.64 conflict-free)

// ---------------- device scratch ------------------------------------------------
__device__ int   g_idx[TOT * KNN];
__device__ float g_t  [TOT * HD];
__device__ float g_q  [TOT * HD];
__device__ float g_kf [TOT * HD];
__device__ float g_v  [TOT * HD];
__device__ float g_agg[TOT * HD];
__device__ float g_part[128 * 2 * HD];
__device__ float g_stats[2 * HD];
__device__ float g_wtf[6 * HD * HD];   // tf32, TRANSPOSED [c][k'] (k permuted per-8)
__device__ unsigned int g_tick1;
__device__ unsigned int g_tick2;

__device__ __forceinline__ float to_tf32(float x) {
    unsigned int r;
    asm("cvt.rna.tf32.f32 %0, %1;" : "=r"(r) : "f"(x));
    return __uint_as_float(r);
}
__device__ __forceinline__ int permk(int k) {          // per-8 k permutation
    return (k & ~7) | ((k & 3) << 1) | ((k >> 2) & 1); // k=t -> 2t ; k=t+4 -> 2t+1
}

__device__ __forceinline__ void cp16(void* dst_smem, const void* src) {
    unsigned int d = (unsigned int)__cvta_generic_to_shared(dst_smem);
    asm volatile("cp.async.cg.shared.global [%0], [%1], 16;\n" :: "r"(d), "l"(src));
}
__device__ __forceinline__ void cp_commit() {
    asm volatile("cp.async.commit_group;\n");
}
template <int N>
__device__ __forceinline__ void cp_wait() {
    asm volatile("cp.async.wait_group %0;\n" :: "n"(N));
}

// ====== weight pre-convert: 6 matrices -> tf32, TRANSPOSED [c][k'] ==============
__global__ __launch_bounds__(512) void conv_kernel(const float* __restrict__ Wd2,
                                                   const float* __restrict__ Wg1,
                                                   const float* __restrict__ Wg2,
                                                   const float* __restrict__ Wphi,
                                                   const float* __restrict__ Wpsi,
                                                   const float* __restrict__ Walpha) {
    int e = blockIdx.x * 512 + threadIdx.x;            // one source float4 each
    const float* srcs[6] = {Wd2, Wg1, Wg2, Wphi, Wpsi, Walpha};
    int m = e / 4096;
    if (m < 6) {
        int idx = e & 4095;
        int k = idx >> 5, c = (idx & 31) * 4;
        float4 v = *(const float4*)&srcs[m][k * 128 + c];
        int kp = permk(k);
        float* dst = g_wtf + m * 16384;
        dst[(c + 0) * 128 + kp] = to_tf32(v.x);
        dst[(c + 1) * 128 + kp] = to_tf32(v.y);
        dst[(c + 2) * 128 + kp] = to_tf32(v.z);
        dst[(c + 3) * 128 + kp] = to_tf32(v.w);
    }
}

// ============================ ball query =========================================
__global__ __launch_bounds__(128) void ball_kernel(const int* __restrict__ coords) {
    __shared__ int sP[NPTS];
    int b = (blockIdx.x * 128) / NPTS;
    int base = b * NPTS;
    for (int j = threadIdx.x; j < NPTS; j += 128) {
        int4 c = *(const int4*)&coords[(size_t)(base + j) * 4];
        sP[j] = c.y | (c.z << 8) | (c.w << 16);
    }
    __syncthreads();
    int qi = blockIdx.x * 128 + threadIdx.x;
    int me = sP[qi - base];
    int qx = me & 255, qy = (me >> 8) & 255, qz = me >> 16;
    int cnt = 0, first = 0;
    int* out = g_idx + (size_t)qi * KNN;
    #pragma unroll 8
    for (int j = 0; j < NPTS; j++) {
        int p = sP[j];
        int dx = qx - (p & 255);
        int dy = qy - ((p >> 8) & 255);
        int dz = qz - (p >> 16);
        int d2 = dx * dx + dy * dy + dz * dz;
        if (d2 <= 100) {
            int gj = base + j;
            out[cnt] = gj;
            if (cnt == 0) first = gj;
            cnt++;
            if (cnt == KNN) break;
        }
    }
    for (int k = cnt; k < KNN; k++) out[k] = first;
}

// ================ t = x @ W_top + b_top, fused BN partials + finalize ===========
__global__ __launch_bounds__(256) void topproj_kernel(const float* __restrict__ x,
                                                      const float* __restrict__ W,
                                                      const float* __restrict__ bias) {
    __shared__ float As[16][128];
    __shared__ float Bs[16][128];
    __shared__ float redS[16][128];
    __shared__ float redSS[16][128];
    __shared__ double dS[2][128];
    __shared__ double dSS[2][128];
    __shared__ bool  sLast;
    int tid = threadIdx.x;
    int ty = tid >> 4, tx = tid & 15;
    int row0 = blockIdx.x * 128;
    float acc[8][8] = {};
    for (int kt = 0; kt < 64; kt += 16) {
        for (int e = tid; e < 512; e += 256) {
            int r = e >> 2, s = e & 3;
            float4 v = *(const float4*)&x[(size_t)(row0 + r) * 64 + kt + s * 4];
            As[s * 4 + 0][r] = v.x; As[s * 4 + 1][r] = v.y;
            As[s * 4 + 2][r] = v.z; As[s * 4 + 3][r] = v.w;
        }
        for (int e = tid; e < 512; e += 256) {
            int k = e >> 5, s = e & 31;
            *(float4*)&Bs[k][s * 4] = *(const float4*)&W[(size_t)(kt + k) * 128 + s * 4];
        }
        __syncthreads();
        #pragma unroll
        for (int k = 0; k < 16; k++) {
            float4 a0 = *(const float4*)&As[k][ty * 8];
            float4 a1 = *(const float4*)&As[k][ty * 8 + 4];
            float4 b0 = *(const float4*)&Bs[k][tx * 8];
            float4 b1 = *(const float4*)&Bs[k][tx * 8 + 4];
            float av[8] = {a0.x, a0.y, a0.z, a0.w, a1.x, a1.y, a1.z, a1.w};
            float bv[8] = {b0.x, b0.y, b0.z, b0.w, b1.x, b1.y, b1.z, b1.w};
            #pragma unroll
            for (int i = 0; i < 8; i++)
                #pragma unroll
                for (int j = 0; j < 8; j++)
                    acc[i][j] += av[i] * bv[j];
        }
        __syncthreads();
    }
    #pragma unroll
    for (int j = 0; j < 8; j++) {
        float b = __ldg(&bias[tx * 8 + j]);
        float s = 0.f, ss = 0.f;
        #pragma unroll
        for (int i = 0; i < 8; i++) {
            float v = acc[i][j] + b;
            g_t[(size_t)(row0 + ty * 8 + i) * 128 + tx * 8 + j] = v;
            s += v; ss += v * v;
        }
        redS[ty][tx * 8 + j] = s;
        redSS[ty][tx * 8 + j] = ss;
    }
    __syncthreads();
    if (tid < 128) {
        float s = 0.f, ss = 0.f;
        #pragma unroll
        for (int u = 0; u < 16; u++) { s += redS[u][tid]; ss += redSS[u][tid]; }
        g_part[blockIdx.x * 256 + tid]       = s;
        g_part[blockIdx.x * 256 + 128 + tid] = ss;
    }
    __threadfence();
    __syncthreads();
    if (tid == 0)
        sLast = (atomicAdd(&g_tick1, 1u) == gridDim.x - 1);
    __syncthreads();
    if (sLast) {
        int c = tid & 127, sub = tid >> 7;   // 2 subs x 128 channels
        double s = 0.0, ss = 0.0;
        for (int b = sub; b < 128; b += 2) {
            s  += (double)g_part[b * 256 + c];
            ss += (double)g_part[b * 256 + 128 + c];
        }
        dS[sub][c] = s; dSS[sub][c] = ss;
        __syncthreads();
        if (tid < 128) {
            double S = dS[0][tid] + dS[1][tid];
            double SS = dSS[0][tid] + dSS[1][tid];
            double m = S / (double)TOT;
            double var = SS / (double)TOT - m * m;
            g_stats[tid]       = (float)m;
            g_stats[128 + tid] = rsqrtf((float)var + 1e-5f);
        }
        if (tid == 0) g_tick1 = 0u;
    }
}

// ============================ tf32 mma GEMM core =================================
// 128x128x128; 16 warps; warp tile 32x32 (wr=wid>>2, wc=wid&3); m16n8k8.
// A [128][AP] row-major tf32 (scalar frag loads, epilogue-friendly).
// W [128][WP] TRANSPOSED [c][k'] tf32 (one LDS.64 per B frag).
__device__ __forceinline__ void gemm_mma(const float* __restrict__ A,
                                         const float* __restrict__ W,
                                         float acc[2][4][4],
                                         int wr, int wc, int g, int t) {
    #pragma unroll
    for (int i = 0; i < 2; i++)
        #pragma unroll
        for (int j = 0; j < 4; j++)
            #pragma unroll
            for (int r = 0; r < 4; r++) acc[i][j][r] = 0.f;
    #pragma unroll 4
    for (int kk = 0; kk < 16; kk++) {
        const int k0 = kk * 8;
        unsigned int a[2][4];
        #pragma unroll
        for (int mi = 0; mi < 2; mi++) {
            const float* ap = A + (size_t)(wr * 32 + mi * 16 + g) * AP + k0 + t;
            a[mi][0] = __float_as_uint(ap[0]);
            a[mi][1] = __float_as_uint(ap[8 * AP]);
            a[mi][2] = __float_as_uint(ap[4]);
            a[mi][3] = __float_as_uint(ap[8 * AP + 4]);
        }
        #pragma unroll
        for (int ni = 0; ni < 4; ni++) {
            const float* bp = W + (size_t)(wc * 32 + ni * 8 + g) * WP + k0 + 2 * t;
            float2 bb = *(const float2*)bp;   // (k=k0+t, c) , (k=k0+t+4, c)
            unsigned int b0 = __float_as_uint(bb.x);
            unsigned int b1 = __float_as_uint(bb.y);
            #pragma unroll
            for (int mi = 0; mi < 2; mi++) {
                asm volatile(
                    "mma.sync.aligned.m16n8k8.row.col.f32.tf32.tf32.f32 "
                    "{%0,%1,%2,%3}, {%4,%5,%6,%7}, {%8,%9}, {%0,%1,%2,%3};\n"
                    : "+f"(acc[mi][ni][0]), "+f"(acc[mi][ni][1]),
                      "+f"(acc[mi][ni][2]), "+f"(acc[mi][ni][3])
                    : "r"(a[mi][0]), "r"(a[mi][1]), "r"(a[mi][2]), "r"(a[mi][3]),
                      "r"(b0), "r"(b1));
            }
        }
    }
}

// shared helper: async copy one 128x128 tf32 weight ([c][k']) into [128][WP] smem
__device__ __forceinline__ void ldW_async(float* dstBase, const float* src, int tid,
                                          int nthreads) {
    for (int e = tid; e < 4096; e += nthreads) {
        int r = e >> 5, c = (e & 31) * 4;
        cp16(dstBase + r * WP + c, src + r * 128 + c);
    }
}

// ============== q,kf,v = normalize(t) @ {W_phi,W_psi,W_alpha} (mma tf32) =========
__global__ __launch_bounds__(512) void qkv_kernel(const float* __restrict__ g1v,
                                                  const float* __restrict__ be1) {
    extern __shared__ float sm[];
    float* BufA = sm;                    // [128][AP]
    float* W0   = BufA + 128 * AP;       // [128][WP]
    float* W1   = W0 + 128 * WP;         // [128][WP]
    __shared__ float sScale[128], sShift[128];
    int tid = threadIdx.x;

    // prefetch Wphi -> W0, Wpsi -> W1
    ldW_async(W0, g_wtf + 3 * 16384, tid, 512);  cp_commit();
    ldW_async(W1, g_wtf + 4 * 16384, tid, 512);  cp_commit();

    if (tid < 128) {
        float m = g_stats[tid], is = g_stats[128 + tid];
        float sc = is * g1v[tid];
        sScale[tid] = sc;
        sShift[tid] = be1[tid] - m * sc;
    }
    __syncthreads();
    int row0 = blockIdx.x * 128;
    for (int e = tid; e < 4096; e += 512) {
        int r = e >> 5, s = (e & 31) * 4;
        float4 v = *(const float4*)&g_t[(size_t)(row0 + r) * 128 + s];
        float4 o;
        o.x = to_tf32(v.x * sScale[s] + sShift[s]);
        o.y = to_tf32(v.y * sScale[s + 1] + sShift[s + 1]);
        o.z = to_tf32(v.z * sScale[s + 2] + sShift[s + 2]);
        o.w = to_tf32(v.w * sScale[s + 3] + sShift[s + 3]);
        *(float4*)&BufA[r * AP + s] = o;
    }

    int wid = tid >> 5, lane = tid & 31;
    int wr = wid >> 2, wc = wid & 3;
    int g = lane >> 2, t = lane & 3;

    #pragma unroll 1
    for (int widx = 0; widx < 3; widx++) {
        float* out = (widx == 0) ? g_q : (widx == 1) ? g_kf : g_v;
        const float* Wb = (widx == 1) ? W1 : W0;
        if (widx < 2) { cp_wait<1>(); } else { cp_wait<0>(); }
        __syncthreads();

        float acc[2][4][4];
        gemm_mma(BufA, Wb, acc, wr, wc, g, t);
        __syncthreads();   // all reads of Wb done before any overwrite

        if (widx == 0) {   // prefetch Walpha -> W0 (free after GEMM0)
            ldW_async(W0, g_wtf + 5 * 16384, tid, 512);
            cp_commit();
        }

        #pragma unroll
        for (int mi = 0; mi < 2; mi++) {
            int r0 = row0 + wr * 32 + mi * 16 + g;
            #pragma unroll
            for (int ni = 0; ni < 4; ni++) {
                int c0 = wc * 32 + ni * 8 + 2 * t;
                *(float2*)&out[(size_t)r0 * 128 + c0] =
                    make_float2(acc[mi][ni][0], acc[mi][ni][1]);
                *(float2*)&out[(size_t)(r0 + 8) * 128 + c0] =
                    make_float2(acc[mi][ni][2], acc[mi][ni][3]);
            }
        }
    }
}

// ============================ fused per-point attention (mma tf32) ==============
__global__ __launch_bounds__(512) void fused_kernel(const int* __restrict__ coords,
                                                    const float* __restrict__ Wd1,
                                                    const float* __restrict__ bd1,
                                                    const float* __restrict__ bd2,
                                                    const float* __restrict__ bg1,
                                                    const float* __restrict__ bg2) {
    extern __shared__ float sm[];
    float* BufA = sm;                      // [128][AP]
    float* W0   = BufA + 128 * AP;         // [128][WP]
    float* W1   = W0 + 128 * WP;           // [128][WP]
    float* sQ   = W1 + 128 * WP;           // [8][128]
    float* sRel = sQ + 8 * 128;            // [128][3]
    float* sWd1 = sRel + 128 * 3;          // [3][128]
    float* sBd1 = sWd1 + 384;              // [128]
    int*   sIdx = (int*)(sBd1 + 128);      // [128]

    int tid = threadIdx.x;
    int p0 = blockIdx.x * 8;
    int wid = tid >> 5, lane = tid & 31;
    int wr = wid >> 2, wc = wid & 3;
    int g = lane >> 2, t = lane & 3;

    // async weight loads: group1 = Wd2 -> W0, group2 = Wg1 -> W1
    ldW_async(W0, g_wtf, tid, 512);           cp_commit();
    ldW_async(W1, g_wtf + 16384, tid, 512);   cp_commit();

    if (tid < 128) {
        sIdx[tid] = g_idx[(size_t)p0 * KNN + tid];
        sBd1[tid] = bd1[tid];
    }
    if (tid < 384) sWd1[tid] = Wd1[tid];
    if (tid < 256) {
        int pp = tid >> 5, s = (tid & 31) * 4;
        *(float4*)&sQ[pp * 128 + s] = *(const float4*)&g_q[(size_t)(p0 + pp) * 128 + s];
    }
    __syncthreads();

    int r0_[2], r1_[2], gi0_[2], gi1_[2];
    #pragma unroll
    for (int mi = 0; mi < 2; mi++) {
        r0_[mi] = wr * 32 + mi * 16 + g;
        r1_[mi] = r0_[mi] + 8;
        gi0_[mi] = sIdx[r0_[mi]];
        gi1_[mi] = sIdx[r1_[mi]];
    }
    // prefetch kf gathers (consumed in epilogue1)
    float2 kf0[2][4], kf1[2][4];
    #pragma unroll
    for (int mi = 0; mi < 2; mi++)
        #pragma unroll
        for (int ni = 0; ni < 4; ni++) {
            int c0 = wc * 32 + ni * 8 + 2 * t;
            kf0[mi][ni] = *(const float2*)&g_kf[(size_t)gi0_[mi] * 128 + c0];
            kf1[mi][ni] = *(const float2*)&g_kf[(size_t)gi1_[mi] * 128 + c0];
        }

    if (tid < 128) {
        int i = p0 + (tid >> 4);
        int j = sIdx[tid];
        int4 ci = *(const int4*)&coords[(size_t)i * 4];
        int4 cj = *(const int4*)&coords[(size_t)j * 4];
        sRel[tid * 3 + 0] = (float)(ci.y - cj.y);
        sRel[tid * 3 + 1] = (float)(ci.z - cj.z);
        sRel[tid * 3 + 2] = (float)(ci.w - cj.w);
    }
    __syncthreads();

    // stage 1: BufA <- tf32(relu(rel @ Wd1 + bd1))
    for (int e = tid; e < 128 * 128; e += 512) {
        int r = e >> 7, c = e & 127;
        float v = sBd1[c] + sRel[r * 3] * sWd1[c] + sRel[r * 3 + 1] * sWd1[128 + c]
                + sRel[r * 3 + 2] * sWd1[256 + c];
        BufA[r * AP + c] = to_tf32(fmaxf(v, 0.f));
    }
    cp_wait<1>();          // Wd2 resident
    __syncthreads();

    // GEMM1: delta = h1 @ Wd2 + bd2  (registers)
    float dlt[2][4][4];
    gemm_mma(BufA, W0, dlt, wr, wc, g, t);
    #pragma unroll
    for (int mi = 0; mi < 2; mi++)
        #pragma unroll
        for (int ni = 0; ni < 4; ni++) {
            int c0 = wc * 32 + ni * 8 + 2 * t;
            float b0 = __ldg(&bd2[c0]), b1 = __ldg(&bd2[c0 + 1]);
            dlt[mi][ni][0] += b0; dlt[mi][ni][1] += b1;
            dlt[mi][ni][2] += b0; dlt[mi][ni][3] += b1;
        }
    __syncthreads();       // all GEMM1 reads of BufA/W0 complete

    // group3: Wg2 -> W0 (W0 now free)
    ldW_async(W0, g_wtf + 32768, tid, 512);
    cp_commit();

    // epilogue1: BufA <- tf32(q - kf + delta)
    #pragma unroll
    for (int mi = 0; mi < 2; mi++) {
        int pl = wr * 2 + mi;
        #pragma unroll
        for (int ni = 0; ni < 4; ni++) {
            int c0 = wc * 32 + ni * 8 + 2 * t;
            float q0 = sQ[pl * 128 + c0], q1 = sQ[pl * 128 + c0 + 1];
            *(float2*)&BufA[r0_[mi] * AP + c0] =
                make_float2(to_tf32(q0 - kf0[mi][ni].x + dlt[mi][ni][0]),
                            to_tf32(q1 - kf0[mi][ni].y + dlt[mi][ni][1]));
            *(float2*)&BufA[r1_[mi] * AP + c0] =
                make_float2(to_tf32(q0 - kf1[mi][ni].x + dlt[mi][ni][2]),
                            to_tf32(q1 - kf1[mi][ni].y + dlt[mi][ni][3]));
        }
    }
    cp_wait<1>();          // Wg1 resident
    __syncthreads();

    // GEMM2: h2 = relu(apre @ Wg1 + bg1)
    float acc2[2][4][4];
    gemm_mma(BufA, W1, acc2, wr, wc, g, t);
    __syncthreads();       // GEMM2 reads of BufA complete
    #pragma unroll
    for (int mi = 0; mi < 2; mi++) {
        #pragma unroll
        for (int ni = 0; ni < 4; ni++) {
            int c0 = wc * 32 + ni * 8 + 2 * t;
            float b0 = __ldg(&bg1[c0]), b1 = __ldg(&bg1[c0 + 1]);
            *(float2*)&BufA[r0_[mi] * AP + c0] =
                make_float2(to_tf32(fmaxf(acc2[mi][ni][0] + b0, 0.f)),
                            to_tf32(fmaxf(acc2[mi][ni][1] + b1, 0.f)));
            *(float2*)&BufA[r1_[mi] * AP + c0] =
                make_float2(to_tf32(fmaxf(acc2[mi][ni][2] + b0, 0.f)),
                            to_tf32(fmaxf(acc2[mi][ni][3] + b1, 0.f)));
        }
    }
    // prefetch v gathers (consumed in softmax)
    float2 v0r[2][4], v1r[2][4];
    #pragma unroll
    for (int mi = 0; mi < 2; mi++)
        #pragma unroll
        for (int ni = 0; ni < 4; ni++) {
            int c0 = wc * 32 + ni * 8 + 2 * t;
            v0r[mi][ni] = *(const float2*)&g_v[(size_t)gi0_[mi] * 128 + c0];
            v1r[mi][ni] = *(const float2*)&g_v[(size_t)gi1_[mi] * 128 + c0];
        }
    cp_wait<0>();          // Wg2 resident
    __syncthreads();

    // GEMM3: logits = h2 @ Wg2 (+bg2 below)
    gemm_mma(BufA, W0, acc2, wr, wc, g, t);

    // softmax over K + aggregate, in registers/shuffles
    #pragma unroll
    for (int mi = 0; mi < 2; mi++) {
        int pl = wr * 2 + mi;
        #pragma unroll
        for (int ni = 0; ni < 4; ni++) {
            int c0 = wc * 32 + ni * 8 + 2 * t;
            float b0 = __ldg(&bg2[c0]), b1 = __ldg(&bg2[c0 + 1]);
            float l00 = acc2[mi][ni][0] + b0, l01 = acc2[mi][ni][1] + b1;
            float l10 = acc2[mi][ni][2] + b0, l11 = acc2[mi][ni][3] + b1;
            float w00 = v0r[mi][ni].x + dlt[mi][ni][0], w01 = v0r[mi][ni].y + dlt[mi][ni][1];
            float w10 = v1r[mi][ni].x + dlt[mi][ni][2], w11 = v1r[mi][ni].y + dlt[mi][ni][3];

            float m0 = fmaxf(l00, l10);
            m0 = fmaxf(m0, __shfl_xor_sync(0xffffffffu, m0, 4));
            m0 = fmaxf(m0, __shfl_xor_sync(0xffffffffu, m0, 8));
            m0 = fmaxf(m0, __shfl_xor_sync(0xffffffffu, m0, 16));
            float m1 = fmaxf(l01, l11);
            m1 = fmaxf(m1, __shfl_xor_sync(0xffffffffu, m1, 4));
            m1 = fmaxf(m1, __shfl_xor_sync(0xffffffffu, m1, 8));
            m1 = fmaxf(m1, __shfl_xor_sync(0xffffffffu, m1, 16));

            float e00 = __expf(l00 - m0), e10 = __expf(l10 - m0);
            float e01 = __expf(l01 - m1), e11 = __expf(l11 - m1);
            float s0 = e00 + e10, s1 = e01 + e11;
            float a0 = e00 * w00 + e10 * w10;
            float a1 = e01 * w01 + e11 * w11;
            s0 += __shfl_xor_sync(0xffffffffu, s0, 4);
            s0 += __shfl_xor_sync(0xffffffffu, s0, 8);
            s0 += __shfl_xor_sync(0xffffffffu, s0, 16);
            s1 += __shfl_xor_sync(0xffffffffu, s1, 4);
            s1 += __shfl_xor_sync(0xffffffffu, s1, 8);
            s1 += __shfl_xor_sync(0xffffffffu, s1, 16);
            a0 += __shfl_xor_sync(0xffffffffu, a0, 4);
            a0 += __shfl_xor_sync(0xffffffffu, a0, 8);
            a0 += __shfl_xor_sync(0xffffffffu, a0, 16);
            a1 += __shfl_xor_sync(0xffffffffu, a1, 4);
            a1 += __shfl_xor_sync(0xffffffffu, a1, 8);
            a1 += __shfl_xor_sync(0xffffffffu, a1, 16);

            if (g == 0)
                *(float2*)&g_agg[(size_t)(p0 + pl) * 128 + c0] =
                    make_float2(a0 / s0, a1 / s1);
        }
    }
}

// ========== down-proj: out = agg @ W_down + b_down, fused BN partials ===========
__global__ __launch_bounds__(256) void down_kernel(const float* __restrict__ W,
                                                   const float* __restrict__ bias,
                                                   float* __restrict__ out) {
    __shared__ float As[16][128];
    __shared__ float Bs[16][64];
    __shared__ float redS[16][64];
    __shared__ float redSS[16][64];
    __shared__ double dS[4][64];
    __shared__ double dSS[4][64];
    __shared__ bool  sLast;
    int tid = threadIdx.x;
    int ty = tid >> 4, tx = tid & 15;
    int row0 = blockIdx.x * 128;
    float acc[8][4] = {};
    for (int kt = 0; kt < 128; kt += 16) {
        for (int e = tid; e < 512; e += 256) {
            int r = e >> 2, s = e & 3;
            float4 v = *(const float4*)&g_agg[(size_t)(row0 + r) * 128 + kt + s * 4];
            As[s * 4 + 0][r] = v.x; As[s * 4 + 1][r] = v.y;
            As[s * 4 + 2][r] = v.z; As[s * 4 + 3][r] = v.w;
        }
        if (tid < 256) {
            int k = tid >> 4, s = tid & 15;
            *(float4*)&Bs[k][s * 4] = *(const float4*)&W[(size_t)(kt + k) * 64 + s * 4];
        }
        __syncthreads();
        #pragma unroll
        for (int k = 0; k < 16; k++) {
            float4 a0 = *(const float4*)&As[k][ty * 8];
            float4 a1 = *(const float4*)&As[k][ty * 8 + 4];
            float4 b = *(const float4*)&Bs[k][tx * 4];
            float av[8] = {a0.x, a0.y, a0.z, a0.w, a1.x, a1.y, a1.z, a1.w};
            float bv[4] = {b.x, b.y, b.z, b.w};
            #pragma unroll
            for (int i = 0; i < 8; i++)
                #pragma unroll
                for (int j = 0; j < 4; j++)
                    acc[i][j] += av[i] * bv[j];
        }
        __syncthreads();
    }
    #pragma unroll
    for (int j = 0; j < 4; j++) {
        float b = __ldg(&bias[tx * 4 + j]);
        float s = 0.f, ss = 0.f;
        #pragma unroll
        for (int i = 0; i < 8; i++) {
            float v = acc[i][j] + b;
            out[(size_t)(row0 + ty * 8 + i) * 64 + tx * 4 + j] = v;
            s += v; ss += v * v;
        }
        redS[ty][tx * 4 + j] = s;
        redSS[ty][tx * 4 + j] = ss;
    }
    __syncthreads();
    if (tid < 64) {
        float s = 0.f, ss = 0.f;
        #pragma unroll
        for (int u = 0; u < 16; u++) { s += redS[u][tid]; ss += redSS[u][tid]; }
        g_part[blockIdx.x * 128 + tid]      = s;
        g_part[blockIdx.x * 128 + 64 + tid] = ss;
    }
    __threadfence();
    __syncthreads();
    if (tid == 0)
        sLast = (atomicAdd(&g_tick2, 1u) == gridDim.x - 1);
    __syncthreads();
    if (sLast) {
        int c = tid & 63, sub = tid >> 6;    // 4 subs x 64 channels
        double s = 0.0, ss = 0.0;
        for (int b = sub; b < 128; b += 4) {
            s  += (double)g_part[b * 128 + c];
            ss += (double)g_part[b * 128 + 64 + c];
        }
        dS[sub][c] = s; dSS[sub][c] = ss;
        __syncthreads();
        if (tid < 64) {
            double S = dS[0][tid] + dS[1][tid] + dS[2][tid] + dS[3][tid];
            double SS = dSS[0][tid] + dSS[1][tid] + dSS[2][tid] + dSS[3][tid];
            double m = S / (double)TOT;
            double var = SS / (double)TOT - m * m;
            g_stats[tid]      = (float)m;
            g_stats[64 + tid] = rsqrtf((float)var + 1e-5f);
        }
        if (tid == 0) g_tick2 = 0u;
    }
}

// ============================ final BN + residual ================================
__global__ __launch_bounds__(256) void final_kernel(const float* __restrict__ x,
                                                    const float* __restrict__ g2,
                                                    const float* __restrict__ be2,
                                                    float* __restrict__ out) {
    int e = blockIdx.x * 256 + threadIdx.x;
    if (e < TOT * IND) {
        int c = e & 63;
        float m = g_stats[c], is = g_stats[IND + c];
        out[e] = (out[e] - m) * is * g2[c] + be2[c] + x[e];
    }
}

// ============================ launch =============================================
extern "C" void kernel_launch(void* const* d_in, const int* in_sizes, int n_in,
                              void* d_out, int out_size) {
    const int*   coords  = (const int*)  d_in[0];
    const float* x       = (const float*)d_in[1];
    const float* W_top   = (const float*)d_in[2];
    const float* b_top   = (const float*)d_in[3];
    const float* g1      = (const float*)d_in[4];
    const float* be1     = (const float*)d_in[5];
    const float* W_phi   = (const float*)d_in[6];
    const float* W_psi   = (const float*)d_in[7];
    const float* W_alpha = (const float*)d_in[8];
    const float* Wd1     = (const float*)d_in[9];
    const float* bd1     = (const float*)d_in[10];
    const float* Wd2     = (const float*)d_in[11];
    const float* bd2     = (const float*)d_in[12];
    const float* Wg1     = (const float*)d_in[13];
    const float* bg1     = (const float*)d_in[14];
    const float* Wg2     = (const float*)d_in[15];
    const float* bg2     = (const float*)d_in[16];
    const float* W_down  = (const float*)d_in[17];
    const float* b_down  = (const float*)d_in[18];
    const float* g2      = (const float*)d_in[19];
    const float* be2     = (const float*)d_in[20];
    float* out = (float*)d_out;

    const size_t SMEM_F = (size_t)(128 * AP + 2 * 128 * WP + 8 * 128 + 128 * 3
                                   + 384 + 128 + 128) * 4;
    const size_t SMEM_Q = (size_t)(128 * AP + 2 * 128 * WP) * 4;
    cudaFuncSetAttribute(fused_kernel, cudaFuncAttributeMaxDynamicSharedMemorySize,
                         (int)SMEM_F);
    cudaFuncSetAttribute(qkv_kernel, cudaFuncAttributeMaxDynamicSharedMemorySize,
                         (int)SMEM_Q);

    conv_kernel<<<48, 512>>>(Wd2, Wg1, Wg2, W_phi, W_psi, W_alpha);
    ball_kernel<<<TOT / 128, 128>>>(coords);
    topproj_kernel<<<TOT / 128, 256>>>(x, W_top, b_top);
    qkv_kernel<<<TOT / 128, 512, SMEM_Q>>>(g1, be1);
    fused_kernel<<<TOT / 8, 512, SMEM_F>>>(coords, Wd1, bd1, bd2, bg1, bg2);
    down_kernel<<<TOT / 128, 256>>>(W_down, b_down, out);
    final_kernel<<<(TOT * IND + 255) / 256, 256>>>(x, g2, be2, out);
}

// round 13
// speedup vs baseline: 1.2526x; 1.1752x over previous
#include <cuda_runtime.h>
#include <cuda_bf16.h>
#include <cstdint>
#include <math.h>

#define TOT   16384
#define NPTS  4096
#define KNN   16
#define HD    128
#define IND   64
#define AP    132    // A-buffer pitch (scalar frag loads)
#define WP    136    // W-buffer pitch ([c][k'] layout; LDS.64 conflict-free)
#define NREL  9261   // 21^3 possible rel vectors
#define NRELP 9344   // padded to 73*128

// ---------------- device scratch ------------------------------------------------
__device__ int   g_idx[TOT * KNN];
__device__ float g_t  [TOT * HD];
__device__ float g_qg [TOT * HD];     // BN(t) @ (Wphi@Wg1)
__device__ float g_kg [TOT * HD];     // BN(t) @ (Wpsi@Wg1)
__device__ float g_v  [TOT * HD];
__device__ float g_agg[TOT * HD];
__device__ float g_part[128 * 2 * HD];
__device__ float g_stats[2 * HD];
__device__ float g_wtf[6 * HD * HD];  // tf32 [c][k']: Wg2,WqG,WkG,Walpha,Wd2,WdG
__device__ float g_comp[3 * HD * HD]; // fp32: Wphi@Wg1, Wpsi@Wg1, Wd2@Wg1
__device__ float g_bdG[HD];           // bd2 @ Wg1
__device__ float g_dtab [NRELP * HD]; // delta(rel) table
__device__ float g_dgtab[NRELP * HD]; // delta(rel)@Wg1 table
__device__ unsigned int g_tick1;
__device__ unsigned int g_tick2;

__device__ __forceinline__ float to_tf32(float x) {
    unsigned int r;
    asm("cvt.rna.tf32.f32 %0, %1;" : "=r"(r) : "f"(x));
    return __uint_as_float(r);
}
__device__ __forceinline__ int permk(int k) {          // per-8 k permutation
    return (k & ~7) | ((k & 3) << 1) | ((k >> 2) & 1); // k=t -> 2t ; k=t+4 -> 2t+1
}

__device__ __forceinline__ void cp16(void* dst_smem, const void* src) {
    unsigned int d = (unsigned int)__cvta_generic_to_shared(dst_smem);
    asm volatile("cp.async.cg.shared.global [%0], [%1], 16;\n" :: "r"(d), "l"(src));
}
__device__ __forceinline__ void cp_commit() {
    asm volatile("cp.async.commit_group;\n");
}
template <int N>
__device__ __forceinline__ void cp_wait() {
    asm volatile("cp.async.wait_group %0;\n" :: "n"(N));
}

// ============ composite weights: {Wphi,Wpsi,Wd2}@Wg1 (fp32) + bdG ===============
__global__ __launch_bounds__(256) void comp_kernel(const float* __restrict__ Wphi,
                                                   const float* __restrict__ Wpsi,
                                                   const float* __restrict__ Wd2,
                                                   const float* __restrict__ Wg1,
                                                   const float* __restrict__ bd2) {
    int m = blockIdx.x;
    int tid = threadIdx.x;
    if (m == 3) {
        if (tid < 128) {
            float s = 0.f;
            for (int k = 0; k < 128; k++)
                s += bd2[k] * Wg1[k * 128 + tid];
            g_bdG[tid] = s;
        }
        return;
    }
    const float* A = (m == 0) ? Wphi : (m == 1) ? Wpsi : Wd2;
    float* C = g_comp + m * 16384;
    __shared__ float As[16][128];
    __shared__ float Bs[16][128];
    int ty = tid >> 4, tx = tid & 15;
    float acc[8][8] = {};
    for (int kt = 0; kt < 128; kt += 16) {
        for (int e = tid; e < 2048; e += 256) {
            int r = e >> 4, k = e & 15;
            As[k][r] = A[r * 128 + kt + k];
        }
        for (int e = tid; e < 2048; e += 256) {
            int k = e >> 7, c = e & 127;
            Bs[k][c] = Wg1[(kt + k) * 128 + c];
        }
        __syncthreads();
        #pragma unroll
        for (int k = 0; k < 16; k++) {
            float av[8], bv[8];
            #pragma unroll
            for (int i = 0; i < 8; i++) av[i] = As[k][ty * 8 + i];
            #pragma unroll
            for (int j = 0; j < 8; j++) bv[j] = Bs[k][tx * 8 + j];
            #pragma unroll
            for (int i = 0; i < 8; i++)
                #pragma unroll
                for (int j = 0; j < 8; j++)
                    acc[i][j] += av[i] * bv[j];
        }
        __syncthreads();
    }
    #pragma unroll
    for (int i = 0; i < 8; i++)
        #pragma unroll
        for (int j = 0; j < 8; j++)
            C[(ty * 8 + i) * 128 + tx * 8 + j] = acc[i][j];
}

// ====== weight pre-convert: 6 matrices -> tf32, TRANSPOSED [c][k'] ==============
// slots: 0=Wg2, 1=WqG, 2=WkG, 3=Walpha, 4=Wd2, 5=WdG
__global__ __launch_bounds__(512) void conv_kernel(const float* __restrict__ Wg2,
                                                   const float* __restrict__ Walpha,
                                                   const float* __restrict__ Wd2) {
    int e = blockIdx.x * 512 + threadIdx.x;            // one source float4 each
    const float* srcs[6] = {Wg2, g_comp, g_comp + 16384, Walpha, Wd2,
                            g_comp + 32768};
    int m = e / 4096;
    if (m < 6) {
        int idx = e & 4095;
        int k = idx >> 5, c = (idx & 31) * 4;
        float4 v = *(const float4*)&srcs[m][k * 128 + c];
        int kp = permk(k);
        float* dst = g_wtf + m * 16384;
        dst[(c + 0) * 128 + kp] = to_tf32(v.x);
        dst[(c + 1) * 128 + kp] = to_tf32(v.y);
        dst[(c + 2) * 128 + kp] = to_tf32(v.z);
        dst[(c + 3) * 128 + kp] = to_tf32(v.w);
    }
}

// ============================ ball query =========================================
__global__ __launch_bounds__(128) void ball_kernel(const int* __restrict__ coords) {
    __shared__ int sP[NPTS];
    int b = (blockIdx.x * 128) / NPTS;
    int base = b * NPTS;
    for (int j = threadIdx.x; j < NPTS; j += 128) {
        int4 c = *(const int4*)&coords[(size_t)(base + j) * 4];
        sP[j] = c.y | (c.z << 8) | (c.w << 16);
    }
    __syncthreads();
    int qi = blockIdx.x * 128 + threadIdx.x;
    int me = sP[qi - base];
    int qx = me & 255, qy = (me >> 8) & 255, qz = me >> 16;
    int cnt = 0, first = 0;
    int* out = g_idx + (size_t)qi * KNN;
    #pragma unroll 8
    for (int j = 0; j < NPTS; j++) {
        int p = sP[j];
        int dx = qx - (p & 255);
        int dy = qy - ((p >> 8) & 255);
        int dz = qz - (p >> 16);
        int d2 = dx * dx + dy * dy + dz * dz;
        if (d2 <= 100) {
            int gj = base + j;
            out[cnt] = gj;
            if (cnt == 0) first = gj;
            cnt++;
            if (cnt == KNN) break;
        }
    }
    for (int k = cnt; k < KNN; k++) out[k] = first;
}

// ================ t = x @ W_top + b_top, fused BN partials + finalize ===========
__global__ __launch_bounds__(256) void topproj_kernel(const float* __restrict__ x,
                                                      const float* __restrict__ W,
                                                      const float* __restrict__ bias) {
    __shared__ float As[16][128];
    __shared__ float Bs[16][128];
    __shared__ float redS[16][128];
    __shared__ float redSS[16][128];
    __shared__ double dS[2][128];
    __shared__ double dSS[2][128];
    __shared__ bool  sLast;
    int tid = threadIdx.x;
    int ty = tid >> 4, tx = tid & 15;
    int row0 = blockIdx.x * 128;
    float acc[8][8] = {};
    for (int kt = 0; kt < 64; kt += 16) {
        for (int e = tid; e < 512; e += 256) {
            int r = e >> 2, s = e & 3;
            float4 v = *(const float4*)&x[(size_t)(row0 + r) * 64 + kt + s * 4];
            As[s * 4 + 0][r] = v.x; As[s * 4 + 1][r] = v.y;
            As[s * 4 + 2][r] = v.z; As[s * 4 + 3][r] = v.w;
        }
        for (int e = tid; e < 512; e += 256) {
            int k = e >> 5, s = e & 31;
            *(float4*)&Bs[k][s * 4] = *(const float4*)&W[(size_t)(kt + k) * 128 + s * 4];
        }
        __syncthreads();
        #pragma unroll
        for (int k = 0; k < 16; k++) {
            float4 a0 = *(const float4*)&As[k][ty * 8];
            float4 a1 = *(const float4*)&As[k][ty * 8 + 4];
            float4 b0 = *(const float4*)&Bs[k][tx * 8];
            float4 b1 = *(const float4*)&Bs[k][tx * 8 + 4];
            float av[8] = {a0.x, a0.y, a0.z, a0.w, a1.x, a1.y, a1.z, a1.w};
            float bv[8] = {b0.x, b0.y, b0.z, b0.w, b1.x, b1.y, b1.z, b1.w};
            #pragma unroll
            for (int i = 0; i < 8; i++)
                #pragma unroll
                for (int j = 0; j < 8; j++)
                    acc[i][j] += av[i] * bv[j];
        }
        __syncthreads();
    }
    #pragma unroll
    for (int j = 0; j < 8; j++) {
        float b = __ldg(&bias[tx * 8 + j]);
        float s = 0.f, ss = 0.f;
        #pragma unroll
        for (int i = 0; i < 8; i++) {
            float v = acc[i][j] + b;
            g_t[(size_t)(row0 + ty * 8 + i) * 128 + tx * 8 + j] = v;
            s += v; ss += v * v;
        }
        redS[ty][tx * 8 + j] = s;
        redSS[ty][tx * 8 + j] = ss;
    }
    __syncthreads();
    if (tid < 128) {
        float s = 0.f, ss = 0.f;
        #pragma unroll
        for (int u = 0; u < 16; u++) { s += redS[u][tid]; ss += redSS[u][tid]; }
        g_part[blockIdx.x * 256 + tid]       = s;
        g_part[blockIdx.x * 256 + 128 + tid] = ss;
    }
    __threadfence();
    __syncthreads();
    if (tid == 0)
        sLast = (atomicAdd(&g_tick1, 1u) == gridDim.x - 1);
    __syncthreads();
    if (sLast) {
        int c = tid & 127, sub = tid >> 7;
        double s = 0.0, ss = 0.0;
        for (int b = sub; b < 128; b += 2) {
            s  += (double)g_part[b * 256 + c];
            ss += (double)g_part[b * 256 + 128 + c];
        }
        dS[sub][c] = s; dSS[sub][c] = ss;
        __syncthreads();
        if (tid < 128) {
            double S = dS[0][tid] + dS[1][tid];
            double SS = dSS[0][tid] + dSS[1][tid];
            double m = S / (double)TOT;
            double var = SS / (double)TOT - m * m;
            g_stats[tid]       = (float)m;
            g_stats[128 + tid] = rsqrtf((float)var + 1e-5f);
        }
        if (tid == 0) g_tick1 = 0u;
    }
}

// ============================ tf32 mma GEMM core =================================
// 128x128x128; 16 warps; warp tile 32x32; m16n8k8.
// A [128][AP] row-major tf32 (scalar frags); W [128][WP] [c][k'] (LDS.64 frags).
__device__ __forceinline__ void gemm_mma(const float* __restrict__ A,
                                         const float* __restrict__ W,
                                         float acc[2][4][4],
                                         int wr, int wc, int g, int t) {
    #pragma unroll
    for (int i = 0; i < 2; i++)
        #pragma unroll
        for (int j = 0; j < 4; j++)
            #pragma unroll
            for (int r = 0; r < 4; r++) acc[i][j][r] = 0.f;
    #pragma unroll 4
    for (int kk = 0; kk < 16; kk++) {
        const int k0 = kk * 8;
        unsigned int a[2][4];
        #pragma unroll
        for (int mi = 0; mi < 2; mi++) {
            const float* ap = A + (size_t)(wr * 32 + mi * 16 + g) * AP + k0 + t;
            a[mi][0] = __float_as_uint(ap[0]);
            a[mi][1] = __float_as_uint(ap[8 * AP]);
            a[mi][2] = __float_as_uint(ap[4]);
            a[mi][3] = __float_as_uint(ap[8 * AP + 4]);
        }
        #pragma unroll
        for (int ni = 0; ni < 4; ni++) {
            const float* bp = W + (size_t)(wc * 32 + ni * 8 + g) * WP + k0 + 2 * t;
            float2 bb = *(const float2*)bp;
            unsigned int b0 = __float_as_uint(bb.x);
            unsigned int b1 = __float_as_uint(bb.y);
            #pragma unroll
            for (int mi = 0; mi < 2; mi++) {
                asm volatile(
                    "mma.sync.aligned.m16n8k8.row.col.f32.tf32.tf32.f32 "
                    "{%0,%1,%2,%3}, {%4,%5,%6,%7}, {%8,%9}, {%0,%1,%2,%3};\n"
                    : "+f"(acc[mi][ni][0]), "+f"(acc[mi][ni][1]),
                      "+f"(acc[mi][ni][2]), "+f"(acc[mi][ni][3])
                    : "r"(a[mi][0]), "r"(a[mi][1]), "r"(a[mi][2]), "r"(a[mi][3]),
                      "r"(b0), "r"(b1));
            }
        }
    }
}

__device__ __forceinline__ void ldW_async(float* dstBase, const float* src, int tid,
                                          int nthreads) {
    for (int e = tid; e < 4096; e += nthreads) {
        int r = e >> 5, c = (e & 31) * 4;
        cp16(dstBase + r * WP + c, src + r * 128 + c);
    }
}

// ============== delta tables: dtab = relu(rel@Wd1+bd1)@Wd2+bd2, dgtab = .. @Wg1 ==
__global__ __launch_bounds__(512) void table_kernel(const float* __restrict__ Wd1,
                                                    const float* __restrict__ bd1,
                                                    const float* __restrict__ bd2) {
    extern __shared__ float sm[];
    float* BufA = sm;                    // [128][AP]
    float* W0   = BufA + 128 * AP;       // [128][WP]  Wd2
    float* W1   = W0 + 128 * WP;         // [128][WP]  WdG
    __shared__ float sWd1[384], sBd1[128];
    int tid = threadIdx.x;
    int row0 = blockIdx.x * 128;

    ldW_async(W0, g_wtf + 4 * 16384, tid, 512);  cp_commit();
    ldW_async(W1, g_wtf + 5 * 16384, tid, 512);  cp_commit();

    if (tid < 384) sWd1[tid] = Wd1[tid];
    if (tid < 128) sBd1[tid] = bd1[tid];
    __syncthreads();

    // stage: BufA <- tf32(relu(rel(idx) @ Wd1 + bd1))
    for (int e = tid; e < 128 * 128; e += 512) {
        int r = e >> 7, c = e & 127;
        int idx = row0 + r;
        if (idx > NREL - 1) idx = NREL - 1;
        float dx = (float)(idx % 21 - 10);
        float dy = (float)((idx / 21) % 21 - 10);
        float dz = (float)(idx / 441 - 10);
        float v = sBd1[c] + dx * sWd1[c] + dy * sWd1[128 + c] + dz * sWd1[256 + c];
        BufA[r * AP + c] = to_tf32(fmaxf(v, 0.f));
    }
    cp_wait<1>();
    __syncthreads();

    int wid = tid >> 5, lane = tid & 31;
    int wr = wid >> 2, wc = wid & 3;
    int g = lane >> 2, t = lane & 3;

    float acc[2][4][4];
    gemm_mma(BufA, W0, acc, wr, wc, g, t);    // delta
    #pragma unroll
    for (int mi = 0; mi < 2; mi++) {
        int r0 = row0 + wr * 32 + mi * 16 + g;
        #pragma unroll
        for (int ni = 0; ni < 4; ni++) {
            int c0 = wc * 32 + ni * 8 + 2 * t;
            float b0 = __ldg(&bd2[c0]), b1 = __ldg(&bd2[c0 + 1]);
            *(float2*)&g_dtab[(size_t)r0 * 128 + c0] =
                make_float2(acc[mi][ni][0] + b0, acc[mi][ni][1] + b1);
            *(float2*)&g_dtab[(size_t)(r0 + 8) * 128 + c0] =
                make_float2(acc[mi][ni][2] + b0, acc[mi][ni][3] + b1);
        }
    }
    cp_wait<0>();
    gemm_mma(BufA, W1, acc, wr, wc, g, t);    // delta @ Wg1
    #pragma unroll
    for (int mi = 0; mi < 2; mi++) {
        int r0 = row0 + wr * 32 + mi * 16 + g;
        #pragma unroll
        for (int ni = 0; ni < 4; ni++) {
            int c0 = wc * 32 + ni * 8 + 2 * t;
            float b0 = g_bdG[c0], b1 = g_bdG[c0 + 1];
            *(float2*)&g_dgtab[(size_t)r0 * 128 + c0] =
                make_float2(acc[mi][ni][0] + b0, acc[mi][ni][1] + b1);
            *(float2*)&g_dgtab[(size_t)(r0 + 8) * 128 + c0] =
                make_float2(acc[mi][ni][2] + b0, acc[mi][ni][3] + b1);
        }
    }
}

// ============== qg,kg,v = normalize(t) @ {WqG,WkG,Walpha} (mma tf32) =============
__global__ __launch_bounds__(512) void qkv_kernel(const float* __restrict__ g1v,
                                                  const float* __restrict__ be1) {
    extern __shared__ float sm[];
    float* BufA = sm;                    // [128][AP]
    float* W0   = BufA + 128 * AP;       // [128][WP]
    float* W1   = W0 + 128 * WP;         // [128][WP]
    __shared__ float sScale[128], sShift[128];
    int tid = threadIdx.x;

    ldW_async(W0, g_wtf + 1 * 16384, tid, 512);  cp_commit();  // WqG
    ldW_async(W1, g_wtf + 2 * 16384, tid, 512);  cp_commit();  // WkG

    if (tid < 128) {
        float m = g_stats[tid], is = g_stats[128 + tid];
        float sc = is * g1v[tid];
        sScale[tid] = sc;
        sShift[tid] = be1[tid] - m * sc;
    }
    __syncthreads();
    int row0 = blockIdx.x * 128;
    for (int e = tid; e < 4096; e += 512) {
        int r = e >> 5, s = (e & 31) * 4;
        float4 v = *(const float4*)&g_t[(size_t)(row0 + r) * 128 + s];
        float4 o;
        o.x = to_tf32(v.x * sScale[s] + sShift[s]);
        o.y = to_tf32(v.y * sScale[s + 1] + sShift[s + 1]);
        o.z = to_tf32(v.z * sScale[s + 2] + sShift[s + 2]);
        o.w = to_tf32(v.w * sScale[s + 3] + sShift[s + 3]);
        *(float4*)&BufA[r * AP + s] = o;
    }

    int wid = tid >> 5, lane = tid & 31;
    int wr = wid >> 2, wc = wid & 3;
    int g = lane >> 2, t = lane & 3;

    #pragma unroll 1
    for (int widx = 0; widx < 3; widx++) {
        float* out = (widx == 0) ? g_qg : (widx == 1) ? g_kg : g_v;
        const float* Wb = (widx == 1) ? W1 : W0;
        if (widx < 2) { cp_wait<1>(); } else { cp_wait<0>(); }
        __syncthreads();

        float acc[2][4][4];
        gemm_mma(BufA, Wb, acc, wr, wc, g, t);
        __syncthreads();

        if (widx == 0) {   // prefetch Walpha -> W0
            ldW_async(W0, g_wtf + 3 * 16384, tid, 512);
            cp_commit();
        }

        #pragma unroll
        for (int mi = 0; mi < 2; mi++) {
            int r0 = row0 + wr * 32 + mi * 16 + g;
            #pragma unroll
            for (int ni = 0; ni < 4; ni++) {
                int c0 = wc * 32 + ni * 8 + 2 * t;
                *(float2*)&out[(size_t)r0 * 128 + c0] =
                    make_float2(acc[mi][ni][0], acc[mi][ni][1]);
                *(float2*)&out[(size_t)(r0 + 8) * 128 + c0] =
                    make_float2(acc[mi][ni][2], acc[mi][ni][3]);
            }
        }
    }
}

// ================== fused attention: ONE GEMM per block now ======================
// h2 = relu(qg_i - kg_j + dgtab[rel] + bg1); logits = h2@Wg2 + bg2;
// agg = softmax_K(logits) . (v_j + dtab[rel])
__global__ __launch_bounds__(512) void fused_kernel(const int* __restrict__ coords,
                                                    const float* __restrict__ bg1,
                                                    const float* __restrict__ bg2) {
    extern __shared__ float sm[];
    float* BufA = sm;                      // [128][AP]
    float* W0   = BufA + 128 * AP;         // [128][WP]  Wg2
    float* sQg  = W0 + 128 * WP;           // [8][128]
    float* sBg1 = sQg + 8 * 128;           // [128]
    int*   sIdx = (int*)(sBg1 + 128);      // [128]
    int*   sCode = sIdx + 128;             // [128]

    int tid = threadIdx.x;
    int p0 = blockIdx.x * 8;
    int wid = tid >> 5, lane = tid & 31;
    int wr = wid >> 2, wc = wid & 3;
    int g = lane >> 2, t = lane & 3;

    ldW_async(W0, g_wtf, tid, 512);  cp_commit();   // Wg2

    if (tid < 128) {
        int j = g_idx[(size_t)p0 * KNN + tid];
        sIdx[tid] = j;
        sBg1[tid] = bg1[tid];
        int i = p0 + (tid >> 4);
        int4 ci = *(const int4*)&coords[(size_t)i * 4];
        int4 cj = *(const int4*)&coords[(size_t)j * 4];
        sCode[tid] = (ci.y - cj.y + 10) + 21 * (ci.z - cj.z + 10)
                   + 441 * (ci.w - cj.w + 10);
    }
    if (tid < 256) {
        int pp = tid >> 5, s = (tid & 31) * 4;
        *(float4*)&sQg[pp * 128 + s] = *(const float4*)&g_qg[(size_t)(p0 + pp) * 128 + s];
    }
    __syncthreads();

    // stage: BufA[r][c] = tf32(relu(qg - kg + dg + bg1))
    for (int e = tid; e < 4096; e += 512) {
        int r = e >> 5, s = (e & 31) * 4;
        int j = sIdx[r], code = sCode[r];
        int pl = r >> 4;
        float4 kg = *(const float4*)&g_kg[(size_t)j * 128 + s];
        float4 dg = *(const float4*)&g_dgtab[(size_t)code * 128 + s];
        float4 qv = *(const float4*)&sQg[pl * 128 + s];
        float4 o;
        o.x = to_tf32(fmaxf(qv.x - kg.x + dg.x + sBg1[s], 0.f));
        o.y = to_tf32(fmaxf(qv.y - kg.y + dg.y + sBg1[s + 1], 0.f));
        o.z = to_tf32(fmaxf(qv.z - kg.z + dg.z + sBg1[s + 2], 0.f));
        o.w = to_tf32(fmaxf(qv.w - kg.w + dg.w + sBg1[s + 3], 0.f));
        *(float4*)&BufA[r * AP + s] = o;
    }
    cp_wait<0>();
    __syncthreads();

    // GEMM: logits = h2 @ Wg2 (+bg2 below)
    float acc2[2][4][4];
    gemm_mma(BufA, W0, acc2, wr, wc, g, t);

    // softmax over K + aggregate
    #pragma unroll
    for (int mi = 0; mi < 2; mi++) {
        int r0 = wr * 32 + mi * 16 + g;
        int r1 = r0 + 8;
        int pl = wr * 2 + mi;
        int gi0 = sIdx[r0], gi1 = sIdx[r1];
        int cd0 = sCode[r0], cd1 = sCode[r1];
        #pragma unroll
        for (int ni = 0; ni < 4; ni++) {
            int c0 = wc * 32 + ni * 8 + 2 * t;
            float b0 = __ldg(&bg2[c0]), b1 = __ldg(&bg2[c0 + 1]);
            float l00 = acc2[mi][ni][0] + b0, l01 = acc2[mi][ni][1] + b1;
            float l10 = acc2[mi][ni][2] + b0, l11 = acc2[mi][ni][3] + b1;
            float2 v0 = *(const float2*)&g_v[(size_t)gi0 * 128 + c0];
            float2 v1 = *(const float2*)&g_v[(size_t)gi1 * 128 + c0];
            float2 d0 = *(const float2*)&g_dtab[(size_t)cd0 * 128 + c0];
            float2 d1 = *(const float2*)&g_dtab[(size_t)cd1 * 128 + c0];
            float w00 = v0.x + d0.x, w01 = v0.y + d0.y;
            float w10 = v1.x + d1.x, w11 = v1.y + d1.y;

            float m0 = fmaxf(l00, l10);
            m0 = fmaxf(m0, __shfl_xor_sync(0xffffffffu, m0, 4));
            m0 = fmaxf(m0, __shfl_xor_sync(0xffffffffu, m0, 8));
            m0 = fmaxf(m0, __shfl_xor_sync(0xffffffffu, m0, 16));
            float m1 = fmaxf(l01, l11);
            m1 = fmaxf(m1, __shfl_xor_sync(0xffffffffu, m1, 4));
            m1 = fmaxf(m1, __shfl_xor_sync(0xffffffffu, m1, 8));
            m1 = fmaxf(m1, __shfl_xor_sync(0xffffffffu, m1, 16));

            float e00 = __expf(l00 - m0), e10 = __expf(l10 - m0);
            float e01 = __expf(l01 - m1), e11 = __expf(l11 - m1);
            float s0 = e00 + e10, s1 = e01 + e11;
            float a0 = e00 * w00 + e10 * w10;
            float a1 = e01 * w01 + e11 * w11;
            s0 += __shfl_xor_sync(0xffffffffu, s0, 4);
            s0 += __shfl_xor_sync(0xffffffffu, s0, 8);
            s0 += __shfl_xor_sync(0xffffffffu, s0, 16);
            s1 += __shfl_xor_sync(0xffffffffu, s1, 4);
            s1 += __shfl_xor_sync(0xffffffffu, s1, 8);
            s1 += __shfl_xor_sync(0xffffffffu, s1, 16);
            a0 += __shfl_xor_sync(0xffffffffu, a0, 4);
            a0 += __shfl_xor_sync(0xffffffffu, a0, 8);
            a0 += __shfl_xor_sync(0xffffffffu, a0, 16);
            a1 += __shfl_xor_sync(0xffffffffu, a1, 4);
            a1 += __shfl_xor_sync(0xffffffffu, a1, 8);
            a1 += __shfl_xor_sync(0xffffffffu, a1, 16);

            if (g == 0)
                *(float2*)&g_agg[(size_t)(p0 + pl) * 128 + c0] =
                    make_float2(a0 / s0, a1 / s1);
        }
    }
}

// ========== down-proj: out = agg @ W_down + b_down, fused BN partials ===========
__global__ __launch_bounds__(256) void down_kernel(const float* __restrict__ W,
                                                   const float* __restrict__ bias,
                                                   float* __restrict__ out) {
    __shared__ float As[16][128];
    __shared__ float Bs[16][64];
    __shared__ float redS[16][64];
    __shared__ float redSS[16][64];
    __shared__ double dS[4][64];
    __shared__ double dSS[4][64];
    __shared__ bool  sLast;
    int tid = threadIdx.x;
    int ty = tid >> 4, tx = tid & 15;
    int row0 = blockIdx.x * 128;
    float acc[8][4] = {};
    for (int kt = 0; kt < 128; kt += 16) {
        for (int e = tid; e < 512; e += 256) {
            int r = e >> 2, s = e & 3;
            float4 v = *(const float4*)&g_agg[(size_t)(row0 + r) * 128 + kt + s * 4];
            As[s * 4 + 0][r] = v.x; As[s * 4 + 1][r] = v.y;
            As[s * 4 + 2][r] = v.z; As[s * 4 + 3][r] = v.w;
        }
        if (tid < 256) {
            int k = tid >> 4, s = tid & 15;
            *(float4*)&Bs[k][s * 4] = *(const float4*)&W[(size_t)(kt + k) * 64 + s * 4];
        }
        __syncthreads();
        #pragma unroll
        for (int k = 0; k < 16; k++) {
            float4 a0 = *(const float4*)&As[k][ty * 8];
            float4 a1 = *(const float4*)&As[k][ty * 8 + 4];
            float4 b = *(const float4*)&Bs[k][tx * 4];
            float av[8] = {a0.x, a0.y, a0.z, a0.w, a1.x, a1.y, a1.z, a1.w};
            float bv[4] = {b.x, b.y, b.z, b.w};
            #pragma unroll
            for (int i = 0; i < 8; i++)
                #pragma unroll
                for (int j = 0; j < 4; j++)
                    acc[i][j] += av[i] * bv[j];
        }
        __syncthreads();
    }
    #pragma unroll
    for (int j = 0; j < 4; j++) {
        float b = __ldg(&bias[tx * 4 + j]);
        float s = 0.f, ss = 0.f;
        #pragma unroll
        for (int i = 0; i < 8; i++) {
            float v = acc[i][j] + b;
            out[(size_t)(row0 + ty * 8 + i) * 64 + tx * 4 + j] = v;
            s += v; ss += v * v;
        }
        redS[ty][tx * 4 + j] = s;
        redSS[ty][tx * 4 + j] = ss;
    }
    __syncthreads();
    if (tid < 64) {
        float s = 0.f, ss = 0.f;
        #pragma unroll
        for (int u = 0; u < 16; u++) { s += redS[u][tid]; ss += redSS[u][tid]; }
        g_part[blockIdx.x * 128 + tid]      = s;
        g_part[blockIdx.x * 128 + 64 + tid] = ss;
    }
    __threadfence();
    __syncthreads();
    if (tid == 0)
        sLast = (atomicAdd(&g_tick2, 1u) == gridDim.x - 1);
    __syncthreads();
    if (sLast) {
        int c = tid & 63, sub = tid >> 6;
        double s = 0.0, ss = 0.0;
        for (int b = sub; b < 128; b += 4) {
            s  += (double)g_part[b * 128 + c];
            ss += (double)g_part[b * 128 + 64 + c];
        }
        dS[sub][c] = s; dSS[sub][c] = ss;
        __syncthreads();
        if (tid < 64) {
            double S = dS[0][tid] + dS[1][tid] + dS[2][tid] + dS[3][tid];
            double SS = dSS[0][tid] + dSS[1][tid] + dSS[2][tid] + dSS[3][tid];
            double m = S / (double)TOT;
            double var = SS / (double)TOT - m * m;
            g_stats[tid]      = (float)m;
            g_stats[64 + tid] = rsqrtf((float)var + 1e-5f);
        }
        if (tid == 0) g_tick2 = 0u;
    }
}

// ============================ final BN + residual ================================
__global__ __launch_bounds__(256) void final_kernel(const float* __restrict__ x,
                                                    const float* __restrict__ g2,
                                                    const float* __restrict__ be2,
                                                    float* __restrict__ out) {
    int e = blockIdx.x * 256 + threadIdx.x;
    if (e < TOT * IND) {
        int c = e & 63;
        float m = g_stats[c], is = g_stats[IND + c];
        out[e] = (out[e] - m) * is * g2[c] + be2[c] + x[e];
    }
}

// ============================ launch =============================================
extern "C" void kernel_launch(void* const* d_in, const int* in_sizes, int n_in,
                              void* d_out, int out_size) {
    const int*   coords  = (const int*)  d_in[0];
    const float* x       = (const float*)d_in[1];
    const float* W_top   = (const float*)d_in[2];
    const float* b_top   = (const float*)d_in[3];
    const float* g1      = (const float*)d_in[4];
    const float* be1     = (const float*)d_in[5];
    const float* W_phi   = (const float*)d_in[6];
    const float* W_psi   = (const float*)d_in[7];
    const float* W_alpha = (const float*)d_in[8];
    const float* Wd1     = (const float*)d_in[9];
    const float* bd1     = (const float*)d_in[10];
    const float* Wd2     = (const float*)d_in[11];
    const float* bd2     = (const float*)d_in[12];
    const float* Wg1     = (const float*)d_in[13];
    const float* bg1     = (const float*)d_in[14];
    const float* Wg2     = (const float*)d_in[15];
    const float* bg2     = (const float*)d_in[16];
    const float* W_down  = (const float*)d_in[17];
    const float* b_down  = (const float*)d_in[18];
    const float* g2      = (const float*)d_in[19];
    const float* be2     = (const float*)d_in[20];
    float* out = (float*)d_out;

    const size_t SMEM_F = (size_t)(128 * AP + 128 * WP + 8 * 128
                                   + 128 + 128 + 128) * 4;
    const size_t SMEM_Q = (size_t)(128 * AP + 2 * 128 * WP) * 4;
    cudaFuncSetAttribute(fused_kernel, cudaFuncAttributeMaxDynamicSharedMemorySize,
                         (int)SMEM_F);
    cudaFuncSetAttribute(qkv_kernel, cudaFuncAttributeMaxDynamicSharedMemorySize,
                         (int)SMEM_Q);
    cudaFuncSetAttribute(table_kernel, cudaFuncAttributeMaxDynamicSharedMemorySize,
                         (int)SMEM_Q);

    comp_kernel<<<4, 256>>>(W_phi, W_psi, Wd2, Wg1, bd2);
    conv_kernel<<<48, 512>>>(Wg2, W_alpha, Wd2);
    ball_kernel<<<TOT / 128, 128>>>(coords);
    table_kernel<<<NRELP / 128, 512, SMEM_Q>>>(Wd1, bd1, bd2);
    topproj_kernel<<<TOT / 128, 256>>>(x, W_top, b_top);
    qkv_kernel<<<TOT / 128, 512, SMEM_Q>>>(g1, be1);
    fused_kernel<<<TOT / 8, 512, SMEM_F>>>(coords, bg1, bg2);
    down_kernel<<<TOT / 128, 256>>>(W_down, b_down, out);
    final_kernel<<<(TOT * IND + 255) / 256, 256>>>(x, g2, be2, out);
}

// round 14
// speedup vs baseline: 1.3165x; 1.0511x over previous
#include <cuda_runtime.h>
#include <cuda_bf16.h>
#include <cstdint>
#include <math.h>

#define TOT   16384
#define NPTS  4096
#define KNN   16
#define HD    128
#define IND   64
#define AP    132    // A-buffer pitch (scalar frag loads)
#define WP    136    // W-buffer pitch ([c][k'] layout; LDS.64 conflict-free)
#define NREL  9261   // 21^3 possible rel vectors
#define NRELP 9344   // padded to 73*128
#define FPTS  16     // points per fused block

// ---------------- device scratch ------------------------------------------------
__device__ int   g_idx[TOT * KNN];
__device__ float g_t  [TOT * HD];
__device__ float g_qg [TOT * HD];     // BN(t) @ (Wphi@Wg1)
__device__ float g_kg [TOT * HD];     // BN(t) @ (Wpsi@Wg1)
__device__ float g_v  [TOT * HD];
__device__ float g_agg[TOT * HD];
__device__ float g_part[128 * 2 * HD];
__device__ float g_stats[2 * HD];
__device__ float g_wtf[6 * HD * HD];  // tf32 [c][k']: Wg2,WqG,WkG,Walpha,Wd2,WdG
__device__ float g_comp[3 * HD * HD]; // fp32: Wphi@Wg1, Wpsi@Wg1, Wd2@Wg1
__device__ float g_bdG[HD];           // bd2 @ Wg1
__device__ float g_dtab [NRELP * HD]; // delta(rel) table
__device__ float g_dgtab[NRELP * HD]; // delta(rel)@Wg1 table
__device__ unsigned int g_tick1;
__device__ unsigned int g_tick2;

__device__ __forceinline__ float to_tf32(float x) {
    unsigned int r;
    asm("cvt.rna.tf32.f32 %0, %1;" : "=r"(r) : "f"(x));
    return __uint_as_float(r);
}
__device__ __forceinline__ int permk(int k) {          // per-8 k permutation
    return (k & ~7) | ((k & 3) << 1) | ((k >> 2) & 1); // k=t -> 2t ; k=t+4 -> 2t+1
}

__device__ __forceinline__ void cp16(void* dst_smem, const void* src) {
    unsigned int d = (unsigned int)__cvta_generic_to_shared(dst_smem);
    asm volatile("cp.async.cg.shared.global [%0], [%1], 16;\n" :: "r"(d), "l"(src));
}
__device__ __forceinline__ void cp_commit() {
    asm volatile("cp.async.commit_group;\n");
}
template <int N>
__device__ __forceinline__ void cp_wait() {
    asm volatile("cp.async.wait_group %0;\n" :: "n"(N));
}

// ============ composite weights: {Wphi,Wpsi,Wd2}@Wg1 (fp32) + bdG ===============
__global__ __launch_bounds__(256) void comp_kernel(const float* __restrict__ Wphi,
                                                   const float* __restrict__ Wpsi,
                                                   const float* __restrict__ Wd2,
                                                   const float* __restrict__ Wg1,
                                                   const float* __restrict__ bd2) {
    int m = blockIdx.x;
    int tid = threadIdx.x;
    if (m == 3) {
        if (tid < 128) {
            float s = 0.f;
            for (int k = 0; k < 128; k++)
                s += bd2[k] * Wg1[k * 128 + tid];
            g_bdG[tid] = s;
        }
        return;
    }
    const float* A = (m == 0) ? Wphi : (m == 1) ? Wpsi : Wd2;
    float* C = g_comp + m * 16384;
    __shared__ float As[16][128];
    __shared__ float Bs[16][128];
    int ty = tid >> 4, tx = tid & 15;
    float acc[8][8] = {};
    for (int kt = 0; kt < 128; kt += 16) {
        for (int e = tid; e < 2048; e += 256) {
            int r = e >> 4, k = e & 15;
            As[k][r] = A[r * 128 + kt + k];
        }
        for (int e = tid; e < 2048; e += 256) {
            int k = e >> 7, c = e & 127;
            Bs[k][c] = Wg1[(kt + k) * 128 + c];
        }
        __syncthreads();
        #pragma unroll
        for (int k = 0; k < 16; k++) {
            float av[8], bv[8];
            #pragma unroll
            for (int i = 0; i < 8; i++) av[i] = As[k][ty * 8 + i];
            #pragma unroll
            for (int j = 0; j < 8; j++) bv[j] = Bs[k][tx * 8 + j];
            #pragma unroll
            for (int i = 0; i < 8; i++)
                #pragma unroll
                for (int j = 0; j < 8; j++)
                    acc[i][j] += av[i] * bv[j];
        }
        __syncthreads();
    }
    #pragma unroll
    for (int i = 0; i < 8; i++)
        #pragma unroll
        for (int j = 0; j < 8; j++)
            C[(ty * 8 + i) * 128 + tx * 8 + j] = acc[i][j];
}

// ====== weight pre-convert: 6 matrices -> tf32, TRANSPOSED [c][k'] ==============
// slots: 0=Wg2, 1=WqG, 2=WkG, 3=Walpha, 4=Wd2, 5=WdG
__global__ __launch_bounds__(512) void conv_kernel(const float* __restrict__ Wg2,
                                                   const float* __restrict__ Walpha,
                                                   const float* __restrict__ Wd2) {
    int e = blockIdx.x * 512 + threadIdx.x;            // one source float4 each
    const float* srcs[6] = {Wg2, g_comp, g_comp + 16384, Walpha, Wd2,
                            g_comp + 32768};
    int m = e / 4096;
    if (m < 6) {
        int idx = e & 4095;
        int k = idx >> 5, c = (idx & 31) * 4;
        float4 v = *(const float4*)&srcs[m][k * 128 + c];
        int kp = permk(k);
        float* dst = g_wtf + m * 16384;
        dst[(c + 0) * 128 + kp] = to_tf32(v.x);
        dst[(c + 1) * 128 + kp] = to_tf32(v.y);
        dst[(c + 2) * 128 + kp] = to_tf32(v.z);
        dst[(c + 3) * 128 + kp] = to_tf32(v.w);
    }
}

// ============================ ball query =========================================
__global__ __launch_bounds__(128) void ball_kernel(const int* __restrict__ coords) {
    __shared__ int sP[NPTS];
    int b = (blockIdx.x * 128) / NPTS;
    int base = b * NPTS;
    for (int j = threadIdx.x; j < NPTS; j += 128) {
        int4 c = *(const int4*)&coords[(size_t)(base + j) * 4];
        sP[j] = c.y | (c.z << 8) | (c.w << 16);
    }
    __syncthreads();
    int qi = blockIdx.x * 128 + threadIdx.x;
    int me = sP[qi - base];
    int qx = me & 255, qy = (me >> 8) & 255, qz = me >> 16;
    int cnt = 0, first = 0;
    int* out = g_idx + (size_t)qi * KNN;
    #pragma unroll 8
    for (int j = 0; j < NPTS; j++) {
        int p = sP[j];
        int dx = qx - (p & 255);
        int dy = qy - ((p >> 8) & 255);
        int dz = qz - (p >> 16);
        int d2 = dx * dx + dy * dy + dz * dz;
        if (d2 <= 100) {
            int gj = base + j;
            out[cnt] = gj;
            if (cnt == 0) first = gj;
            cnt++;
            if (cnt == KNN) break;
        }
    }
    for (int k = cnt; k < KNN; k++) out[k] = first;
}

// ================ t = x @ W_top + b_top, fused BN partials + finalize ===========
__global__ __launch_bounds__(256) void topproj_kernel(const float* __restrict__ x,
                                                      const float* __restrict__ W,
                                                      const float* __restrict__ bias) {
    __shared__ float As[16][128];
    __shared__ float Bs[16][128];
    __shared__ float redS[16][128];
    __shared__ float redSS[16][128];
    __shared__ double dS[2][128];
    __shared__ double dSS[2][128];
    __shared__ bool  sLast;
    int tid = threadIdx.x;
    int ty = tid >> 4, tx = tid & 15;
    int row0 = blockIdx.x * 128;
    float acc[8][8] = {};
    for (int kt = 0; kt < 64; kt += 16) {
        for (int e = tid; e < 512; e += 256) {
            int r = e >> 2, s = e & 3;
            float4 v = *(const float4*)&x[(size_t)(row0 + r) * 64 + kt + s * 4];
            As[s * 4 + 0][r] = v.x; As[s * 4 + 1][r] = v.y;
            As[s * 4 + 2][r] = v.z; As[s * 4 + 3][r] = v.w;
        }
        for (int e = tid; e < 512; e += 256) {
            int k = e >> 5, s = e & 31;
            *(float4*)&Bs[k][s * 4] = *(const float4*)&W[(size_t)(kt + k) * 128 + s * 4];
        }
        __syncthreads();
        #pragma unroll
        for (int k = 0; k < 16; k++) {
            float4 a0 = *(const float4*)&As[k][ty * 8];
            float4 a1 = *(const float4*)&As[k][ty * 8 + 4];
            float4 b0 = *(const float4*)&Bs[k][tx * 8];
            float4 b1 = *(const float4*)&Bs[k][tx * 8 + 4];
            float av[8] = {a0.x, a0.y, a0.z, a0.w, a1.x, a1.y, a1.z, a1.w};
            float bv[8] = {b0.x, b0.y, b0.z, b0.w, b1.x, b1.y, b1.z, b1.w};
            #pragma unroll
            for (int i = 0; i < 8; i++)
                #pragma unroll
                for (int j = 0; j < 8; j++)
                    acc[i][j] += av[i] * bv[j];
        }
        __syncthreads();
    }
    #pragma unroll
    for (int j = 0; j < 8; j++) {
        float b = __ldg(&bias[tx * 8 + j]);
        float s = 0.f, ss = 0.f;
        #pragma unroll
        for (int i = 0; i < 8; i++) {
            float v = acc[i][j] + b;
            g_t[(size_t)(row0 + ty * 8 + i) * 128 + tx * 8 + j] = v;
            s += v; ss += v * v;
        }
        redS[ty][tx * 8 + j] = s;
        redSS[ty][tx * 8 + j] = ss;
    }
    __syncthreads();
    if (tid < 128) {
        float s = 0.f, ss = 0.f;
        #pragma unroll
        for (int u = 0; u < 16; u++) { s += redS[u][tid]; ss += redSS[u][tid]; }
        g_part[blockIdx.x * 256 + tid]       = s;
        g_part[blockIdx.x * 256 + 128 + tid] = ss;
    }
    __threadfence();
    __syncthreads();
    if (tid == 0)
        sLast = (atomicAdd(&g_tick1, 1u) == gridDim.x - 1);
    __syncthreads();
    if (sLast) {
        int c = tid & 127, sub = tid >> 7;
        double s = 0.0, ss = 0.0;
        for (int b = sub; b < 128; b += 2) {
            s  += (double)g_part[b * 256 + c];
            ss += (double)g_part[b * 256 + 128 + c];
        }
        dS[sub][c] = s; dSS[sub][c] = ss;
        __syncthreads();
        if (tid < 128) {
            double S = dS[0][tid] + dS[1][tid];
            double SS = dSS[0][tid] + dSS[1][tid];
            double m = S / (double)TOT;
            double var = SS / (double)TOT - m * m;
            g_stats[tid]       = (float)m;
            g_stats[128 + tid] = rsqrtf((float)var + 1e-5f);
        }
        if (tid == 0) g_tick1 = 0u;
    }
}

// ============================ tf32 mma GEMM core =================================
// M-rows x 128 x 128; warp tile 32x32; m16n8k8.
// A [M][AP] row-major tf32 (scalar frags); W [128][WP] [c][k'] (LDS.64 frags).
__device__ __forceinline__ void gemm_mma(const float* __restrict__ A,
                                         const float* __restrict__ W,
                                         float acc[2][4][4],
                                         int wr, int wc, int g, int t) {
    #pragma unroll
    for (int i = 0; i < 2; i++)
        #pragma unroll
        for (int j = 0; j < 4; j++)
            #pragma unroll
            for (int r = 0; r < 4; r++) acc[i][j][r] = 0.f;
    #pragma unroll 4
    for (int kk = 0; kk < 16; kk++) {
        const int k0 = kk * 8;
        unsigned int a[2][4];
        #pragma unroll
        for (int mi = 0; mi < 2; mi++) {
            const float* ap = A + (size_t)(wr * 32 + mi * 16 + g) * AP + k0 + t;
            a[mi][0] = __float_as_uint(ap[0]);
            a[mi][1] = __float_as_uint(ap[8 * AP]);
            a[mi][2] = __float_as_uint(ap[4]);
            a[mi][3] = __float_as_uint(ap[8 * AP + 4]);
        }
        #pragma unroll
        for (int ni = 0; ni < 4; ni++) {
            const float* bp = W + (size_t)(wc * 32 + ni * 8 + g) * WP + k0 + 2 * t;
            float2 bb = *(const float2*)bp;
            unsigned int b0 = __float_as_uint(bb.x);
            unsigned int b1 = __float_as_uint(bb.y);
            #pragma unroll
            for (int mi = 0; mi < 2; mi++) {
                asm volatile(
                    "mma.sync.aligned.m16n8k8.row.col.f32.tf32.tf32.f32 "
                    "{%0,%1,%2,%3}, {%4,%5,%6,%7}, {%8,%9}, {%0,%1,%2,%3};\n"
                    : "+f"(acc[mi][ni][0]), "+f"(acc[mi][ni][1]),
                      "+f"(acc[mi][ni][2]), "+f"(acc[mi][ni][3])
                    : "r"(a[mi][0]), "r"(a[mi][1]), "r"(a[mi][2]), "r"(a[mi][3]),
                      "r"(b0), "r"(b1));
            }
        }
    }
}

__device__ __forceinline__ void ldW_async(float* dstBase, const float* src, int tid,
                                          int nthreads) {
    for (int e = tid; e < 4096; e += nthreads) {
        int r = e >> 5, c = (e & 31) * 4;
        cp16(dstBase + r * WP + c, src + r * 128 + c);
    }
}

// ============== delta tables: dtab = relu(rel@Wd1+bd1)@Wd2+bd2, dgtab = .. @Wg1 ==
__global__ __launch_bounds__(512) void table_kernel(const float* __restrict__ Wd1,
                                                    const float* __restrict__ bd1,
                                                    const float* __restrict__ bd2) {
    extern __shared__ float sm[];
    float* BufA = sm;                    // [128][AP]
    float* W0   = BufA + 128 * AP;       // [128][WP]  Wd2
    float* W1   = W0 + 128 * WP;         // [128][WP]  WdG
    __shared__ float sWd1[384], sBd1[128];
    int tid = threadIdx.x;
    int row0 = blockIdx.x * 128;

    ldW_async(W0, g_wtf + 4 * 16384, tid, 512);  cp_commit();
    ldW_async(W1, g_wtf + 5 * 16384, tid, 512);  cp_commit();

    if (tid < 384) sWd1[tid] = Wd1[tid];
    if (tid < 128) sBd1[tid] = bd1[tid];
    __syncthreads();

    for (int e = tid; e < 128 * 128; e += 512) {
        int r = e >> 7, c = e & 127;
        int idx = row0 + r;
        if (idx > NREL - 1) idx = NREL - 1;
        float dx = (float)(idx % 21 - 10);
        float dy = (float)((idx / 21) % 21 - 10);
        float dz = (float)(idx / 441 - 10);
        float v = sBd1[c] + dx * sWd1[c] + dy * sWd1[128 + c] + dz * sWd1[256 + c];
        BufA[r * AP + c] = to_tf32(fmaxf(v, 0.f));
    }
    cp_wait<1>();
    __syncthreads();

    int wid = tid >> 5, lane = tid & 31;
    int wr = wid >> 2, wc = wid & 3;
    int g = lane >> 2, t = lane & 3;

    float acc[2][4][4];
    gemm_mma(BufA, W0, acc, wr, wc, g, t);    // delta
    #pragma unroll
    for (int mi = 0; mi < 2; mi++) {
        int r0 = row0 + wr * 32 + mi * 16 + g;
        #pragma unroll
        for (int ni = 0; ni < 4; ni++) {
            int c0 = wc * 32 + ni * 8 + 2 * t;
            float b0 = __ldg(&bd2[c0]), b1 = __ldg(&bd2[c0 + 1]);
            *(float2*)&g_dtab[(size_t)r0 * 128 + c0] =
                make_float2(acc[mi][ni][0] + b0, acc[mi][ni][1] + b1);
            *(float2*)&g_dtab[(size_t)(r0 + 8) * 128 + c0] =
                make_float2(acc[mi][ni][2] + b0, acc[mi][ni][3] + b1);
        }
    }
    cp_wait<0>();
    gemm_mma(BufA, W1, acc, wr, wc, g, t);    // delta @ Wg1
    #pragma unroll
    for (int mi = 0; mi < 2; mi++) {
        int r0 = row0 + wr * 32 + mi * 16 + g;
        #pragma unroll
        for (int ni = 0; ni < 4; ni++) {
            int c0 = wc * 32 + ni * 8 + 2 * t;
            float b0 = g_bdG[c0], b1 = g_bdG[c0 + 1];
            *(float2*)&g_dgtab[(size_t)r0 * 128 + c0] =
                make_float2(acc[mi][ni][0] + b0, acc[mi][ni][1] + b1);
            *(float2*)&g_dgtab[(size_t)(r0 + 8) * 128 + c0] =
                make_float2(acc[mi][ni][2] + b0, acc[mi][ni][3] + b1);
        }
    }
}

// ============== qg,kg,v = normalize(t) @ {WqG,WkG,Walpha} (mma tf32) =============
__global__ __launch_bounds__(512) void qkv_kernel(const float* __restrict__ g1v,
                                                  const float* __restrict__ be1) {
    extern __shared__ float sm[];
    float* BufA = sm;                    // [128][AP]
    float* W0   = BufA + 128 * AP;       // [128][WP]
    float* W1   = W0 + 128 * WP;         // [128][WP]
    __shared__ float sScale[128], sShift[128];
    int tid = threadIdx.x;

    ldW_async(W0, g_wtf + 1 * 16384, tid, 512);  cp_commit();  // WqG
    ldW_async(W1, g_wtf + 2 * 16384, tid, 512);  cp_commit();  // WkG

    if (tid < 128) {
        float m = g_stats[tid], is = g_stats[128 + tid];
        float sc = is * g1v[tid];
        sScale[tid] = sc;
        sShift[tid] = be1[tid] - m * sc;
    }
    __syncthreads();
    int row0 = blockIdx.x * 128;
    for (int e = tid; e < 4096; e += 512) {
        int r = e >> 5, s = (e & 31) * 4;
        float4 v = *(const float4*)&g_t[(size_t)(row0 + r) * 128 + s];
        float4 o;
        o.x = to_tf32(v.x * sScale[s] + sShift[s]);
        o.y = to_tf32(v.y * sScale[s + 1] + sShift[s + 1]);
        o.z = to_tf32(v.z * sScale[s + 2] + sShift[s + 2]);
        o.w = to_tf32(v.w * sScale[s + 3] + sShift[s + 3]);
        *(float4*)&BufA[r * AP + s] = o;
    }

    int wid = tid >> 5, lane = tid & 31;
    int wr = wid >> 2, wc = wid & 3;
    int g = lane >> 2, t = lane & 3;

    #pragma unroll 1
    for (int widx = 0; widx < 3; widx++) {
        float* out = (widx == 0) ? g_qg : (widx == 1) ? g_kg : g_v;
        const float* Wb = (widx == 1) ? W1 : W0;
        if (widx < 2) { cp_wait<1>(); } else { cp_wait<0>(); }
        __syncthreads();

        float acc[2][4][4];
        gemm_mma(BufA, Wb, acc, wr, wc, g, t);
        __syncthreads();

        if (widx == 0) {
            ldW_async(W0, g_wtf + 3 * 16384, tid, 512);
            cp_commit();
        }

        #pragma unroll
        for (int mi = 0; mi < 2; mi++) {
            int r0 = row0 + wr * 32 + mi * 16 + g;
            #pragma unroll
            for (int ni = 0; ni < 4; ni++) {
                int c0 = wc * 32 + ni * 8 + 2 * t;
                *(float2*)&out[(size_t)r0 * 128 + c0] =
                    make_float2(acc[mi][ni][0], acc[mi][ni][1]);
                *(float2*)&out[(size_t)(r0 + 8) * 128 + c0] =
                    make_float2(acc[mi][ni][2], acc[mi][ni][3]);
            }
        }
    }
}

// ================== fused attention: 16 points/block, 1024 threads ===============
// h2 = relu(qg_i - kg_j + dgtab[rel] + bg1); logits = h2@Wg2 + bg2;
// agg = softmax_K(logits) . (v_j + dtab[rel])
__global__ __launch_bounds__(1024) void fused_kernel(const int* __restrict__ coords,
                                                     const float* __restrict__ bg1,
                                                     const float* __restrict__ bg2) {
    extern __shared__ float sm[];
    float* BufA = sm;                      // [256][AP]
    float* W0   = BufA + 256 * AP;         // [128][WP]  Wg2
    float* sQg  = W0 + 128 * WP;           // [16][128]
    float* sBg1 = sQg + FPTS * 128;        // [128]
    int*   sIdx = (int*)(sBg1 + 128);      // [256]
    int*   sCode = sIdx + 256;             // [256]

    int tid = threadIdx.x;
    int p0 = blockIdx.x * FPTS;
    int wid = tid >> 5, lane = tid & 31;
    int wr = wid >> 2, wc = wid & 3;     // wr 0..7, wc 0..3
    int g = lane >> 2, t = lane & 3;

    ldW_async(W0, g_wtf, tid, 1024);  cp_commit();   // Wg2

    if (tid < 256) {
        int j = g_idx[(size_t)p0 * KNN + tid];
        sIdx[tid] = j;
        int i = p0 + (tid >> 4);
        int4 ci = *(const int4*)&coords[(size_t)i * 4];
        int4 cj = *(const int4*)&coords[(size_t)j * 4];
        sCode[tid] = (ci.y - cj.y + 10) + 21 * (ci.z - cj.z + 10)
                   + 441 * (ci.w - cj.w + 10);
    }
    if (tid < 128) sBg1[tid] = bg1[tid];
    if (tid < 512) {
        int pp = tid >> 5, s = (tid & 31) * 4;
        *(float4*)&sQg[pp * 128 + s] = *(const float4*)&g_qg[(size_t)(p0 + pp) * 128 + s];
    }
    __syncthreads();

    // stage: BufA[r][c] = tf32(relu(qg - kg + dg + bg1)), 256 rows
    for (int e = tid; e < 8192; e += 1024) {
        int r = e >> 5, s = (e & 31) * 4;
        int j = sIdx[r], code = sCode[r];
        int pl = r >> 4;
        float4 kg = *(const float4*)&g_kg[(size_t)j * 128 + s];
        float4 dg = *(const float4*)&g_dgtab[(size_t)code * 128 + s];
        float4 qv = *(const float4*)&sQg[pl * 128 + s];
        float4 o;
        o.x = to_tf32(fmaxf(qv.x - kg.x + dg.x + sBg1[s], 0.f));
        o.y = to_tf32(fmaxf(qv.y - kg.y + dg.y + sBg1[s + 1], 0.f));
        o.z = to_tf32(fmaxf(qv.z - kg.z + dg.z + sBg1[s + 2], 0.f));
        o.w = to_tf32(fmaxf(qv.w - kg.w + dg.w + sBg1[s + 3], 0.f));
        *(float4*)&BufA[r * AP + s] = o;
    }
    cp_wait<0>();
    __syncthreads();

    // GEMM: logits = h2 @ Wg2 (+bg2 below); 256x128x128, 32 warps
    float acc2[2][4][4];
    gemm_mma(BufA, W0, acc2, wr, wc, g, t);

    // softmax over K + aggregate
    #pragma unroll
    for (int mi = 0; mi < 2; mi++) {
        int r0 = wr * 32 + mi * 16 + g;
        int r1 = r0 + 8;
        int pl = wr * 2 + mi;
        int gi0 = sIdx[r0], gi1 = sIdx[r1];
        int cd0 = sCode[r0], cd1 = sCode[r1];
        #pragma unroll
        for (int ni = 0; ni < 4; ni++) {
            int c0 = wc * 32 + ni * 8 + 2 * t;
            float b0 = __ldg(&bg2[c0]), b1 = __ldg(&bg2[c0 + 1]);
            float l00 = acc2[mi][ni][0] + b0, l01 = acc2[mi][ni][1] + b1;
            float l10 = acc2[mi][ni][2] + b0, l11 = acc2[mi][ni][3] + b1;
            float2 v0 = *(const float2*)&g_v[(size_t)gi0 * 128 + c0];
            float2 v1 = *(const float2*)&g_v[(size_t)gi1 * 128 + c0];
            float2 d0 = *(const float2*)&g_dtab[(size_t)cd0 * 128 + c0];
            float2 d1 = *(const float2*)&g_dtab[(size_t)cd1 * 128 + c0];
            float w00 = v0.x + d0.x, w01 = v0.y + d0.y;
            float w10 = v1.x + d1.x, w11 = v1.y + d1.y;

            float m0 = fmaxf(l00, l10);
            m0 = fmaxf(m0, __shfl_xor_sync(0xffffffffu, m0, 4));
            m0 = fmaxf(m0, __shfl_xor_sync(0xffffffffu, m0, 8));
            m0 = fmaxf(m0, __shfl_xor_sync(0xffffffffu, m0, 16));
            float m1 = fmaxf(l01, l11);
            m1 = fmaxf(m1, __shfl_xor_sync(0xffffffffu, m1, 4));
            m1 = fmaxf(m1, __shfl_xor_sync(0xffffffffu, m1, 8));
            m1 = fmaxf(m1, __shfl_xor_sync(0xffffffffu, m1, 16));

            float e00 = __expf(l00 - m0), e10 = __expf(l10 - m0);
            float e01 = __expf(l01 - m1), e11 = __expf(l11 - m1);
            float s0 = e00 + e10, s1 = e01 + e11;
            float a0 = e00 * w00 + e10 * w10;
            float a1 = e01 * w01 + e11 * w11;
            s0 += __shfl_xor_sync(0xffffffffu, s0, 4);
            s0 += __shfl_xor_sync(0xffffffffu, s0, 8);
            s0 += __shfl_xor_sync(0xffffffffu, s0, 16);
            s1 += __shfl_xor_sync(0xffffffffu, s1, 4);
            s1 += __shfl_xor_sync(0xffffffffu, s1, 8);
            s1 += __shfl_xor_sync(0xffffffffu, s1, 16);
            a0 += __shfl_xor_sync(0xffffffffu, a0, 4);
            a0 += __shfl_xor_sync(0xffffffffu, a0, 8);
            a0 += __shfl_xor_sync(0xffffffffu, a0, 16);
            a1 += __shfl_xor_sync(0xffffffffu, a1, 4);
            a1 += __shfl_xor_sync(0xffffffffu, a1, 8);
            a1 += __shfl_xor_sync(0xffffffffu, a1, 16);

            if (g == 0)
                *(float2*)&g_agg[(size_t)(p0 + pl) * 128 + c0] =
                    make_float2(a0 / s0, a1 / s1);
        }
    }
}

// ========== down-proj: out = agg @ W_down + b_down, fused BN partials ===========
__global__ __launch_bounds__(256) void down_kernel(const float* __restrict__ W,
                                                   const float* __restrict__ bias,
                                                   float* __restrict__ out) {
    __shared__ float As[16][128];
    __shared__ float Bs[16][64];
    __shared__ float redS[16][64];
    __shared__ float redSS[16][64];
    __shared__ double dS[4][64];
    __shared__ double dSS[4][64];
    __shared__ bool  sLast;
    int tid = threadIdx.x;
    int ty = tid >> 4, tx = tid & 15;
    int row0 = blockIdx.x * 128;
    float acc[8][4] = {};
    for (int kt = 0; kt < 128; kt += 16) {
        for (int e = tid; e < 512; e += 256) {
            int r = e >> 2, s = e & 3;
            float4 v = *(const float4*)&g_agg[(size_t)(row0 + r) * 128 + kt + s * 4];
            As[s * 4 + 0][r] = v.x; As[s * 4 + 1][r] = v.y;
            As[s * 4 + 2][r] = v.z; As[s * 4 + 3][r] = v.w;
        }
        if (tid < 256) {
            int k = tid >> 4, s = tid & 15;
            *(float4*)&Bs[k][s * 4] = *(const float4*)&W[(size_t)(kt + k) * 64 + s * 4];
        }
        __syncthreads();
        #pragma unroll
        for (int k = 0; k < 16; k++) {
            float4 a0 = *(const float4*)&As[k][ty * 8];
            float4 a1 = *(const float4*)&As[k][ty * 8 + 4];
            float4 b = *(const float4*)&Bs[k][tx * 4];
            float av[8] = {a0.x, a0.y, a0.z, a0.w, a1.x, a1.y, a1.z, a1.w};
            float bv[4] = {b.x, b.y, b.z, b.w};
            #pragma unroll
            for (int i = 0; i < 8; i++)
                #pragma unroll
                for (int j = 0; j < 4; j++)
                    acc[i][j] += av[i] * bv[j];
        }
        __syncthreads();
    }
    #pragma unroll
    for (int j = 0; j < 4; j++) {
        float b = __ldg(&bias[tx * 4 + j]);
        float s = 0.f, ss = 0.f;
        #pragma unroll
        for (int i = 0; i < 8; i++) {
            float v = acc[i][j] + b;
            out[(size_t)(row0 + ty * 8 + i) * 64 + tx * 4 + j] = v;
            s += v; ss += v * v;
        }
        redS[ty][tx * 4 + j] = s;
        redSS[ty][tx * 4 + j] = ss;
    }
    __syncthreads();
    if (tid < 64) {
        float s = 0.f, ss = 0.f;
        #pragma unroll
        for (int u = 0; u < 16; u++) { s += redS[u][tid]; ss += redSS[u][tid]; }
        g_part[blockIdx.x * 128 + tid]      = s;
        g_part[blockIdx.x * 128 + 64 + tid] = ss;
    }
    __threadfence();
    __syncthreads();
    if (tid == 0)
        sLast = (atomicAdd(&g_tick2, 1u) == gridDim.x - 1);
    __syncthreads();
    if (sLast) {
        int c = tid & 63, sub = tid >> 6;
        double s = 0.0, ss = 0.0;
        for (int b = sub; b < 128; b += 4) {
            s  += (double)g_part[b * 128 + c];
            ss += (double)g_part[b * 128 + 64 + c];
        }
        dS[sub][c] = s; dSS[sub][c] = ss;
        __syncthreads();
        if (tid < 64) {
            double S = dS[0][tid] + dS[1][tid] + dS[2][tid] + dS[3][tid];
            double SS = dSS[0][tid] + dSS[1][tid] + dSS[2][tid] + dSS[3][tid];
            double m = S / (double)TOT;
            double var = SS / (double)TOT - m * m;
            g_stats[tid]      = (float)m;
            g_stats[64 + tid] = rsqrtf((float)var + 1e-5f);
        }
        if (tid == 0) g_tick2 = 0u;
    }
}

// ============================ final BN + residual ================================
__global__ __launch_bounds__(256) void final_kernel(const float* __restrict__ x,
                                                    const float* __restrict__ g2,
                                                    const float* __restrict__ be2,
                                                    float* __restrict__ out) {
    int e = blockIdx.x * 256 + threadIdx.x;
    if (e < TOT * IND) {
        int c = e & 63;
        float m = g_stats[c], is = g_stats[IND + c];
        out[e] = (out[e] - m) * is * g2[c] + be2[c] + x[e];
    }
}

// ============================ launch =============================================
extern "C" void kernel_launch(void* const* d_in, const int* in_sizes, int n_in,
                              void* d_out, int out_size) {
    const int*   coords  = (const int*)  d_in[0];
    const float* x       = (const float*)d_in[1];
    const float* W_top   = (const float*)d_in[2];
    const float* b_top   = (const float*)d_in[3];
    const float* g1      = (const float*)d_in[4];
    const float* be1     = (const float*)d_in[5];
    const float* W_phi   = (const float*)d_in[6];
    const float* W_psi   = (const float*)d_in[7];
    const float* W_alpha = (const float*)d_in[8];
    const float* Wd1     = (const float*)d_in[9];
    const float* bd1     = (const float*)d_in[10];
    const float* Wd2     = (const float*)d_in[11];
    const float* bd2     = (const float*)d_in[12];
    const float* Wg1     = (const float*)d_in[13];
    const float* bg1     = (const float*)d_in[14];
    const float* Wg2     = (const float*)d_in[15];
    const float* bg2     = (const float*)d_in[16];
    const float* W_down  = (const float*)d_in[17];
    const float* b_down  = (const float*)d_in[18];
    const float* g2      = (const float*)d_in[19];
    const float* be2     = (const float*)d_in[20];
    float* out = (float*)d_out;

    const size_t SMEM_F = (size_t)(256 * AP + 128 * WP + FPTS * 128
                                   + 128 + 256 + 256) * 4;
    const size_t SMEM_Q = (size_t)(128 * AP + 2 * 128 * WP) * 4;
    cudaFuncSetAttribute(fused_kernel, cudaFuncAttributeMaxDynamicSharedMemorySize,
                         (int)SMEM_F);
    cudaFuncSetAttribute(qkv_kernel, cudaFuncAttributeMaxDynamicSharedMemorySize,
                         (int)SMEM_Q);
    cudaFuncSetAttribute(table_kernel, cudaFuncAttributeMaxDynamicSharedMemorySize,
                         (int)SMEM_Q);

    comp_kernel<<<4, 256>>>(W_phi, W_psi, Wd2, Wg1, bd2);
    conv_kernel<<<48, 512>>>(Wg2, W_alpha, Wd2);
    ball_kernel<<<TOT / 128, 128>>>(coords);
    table_kernel<<<NRELP / 128, 512, SMEM_Q>>>(Wd1, bd1, bd2);
    topproj_kernel<<<TOT / 128, 256>>>(x, W_top, b_top);
    qkv_kernel<<<TOT / 128, 512, SMEM_Q>>>(g1, be1);
    fused_kernel<<<TOT / FPTS, 1024, SMEM_F>>>(coords, bg1, bg2);
    down_kernel<<<TOT / 128, 256>>>(W_down, b_down, out);
    final_kernel<<<(TOT * IND + 255) / 256, 256>>>(x, g2, be2, out);
}

// round 15
// speedup vs baseline: 1.3266x; 1.0077x over previous
#include <cuda_runtime.h>
#include <cuda_bf16.h>
#include <cstdint>
#include <math.h>

#define TOT   16384
#define NPTS  4096
#define KNN   16
#define HD    128
#define IND   64
#define AP    132    // A-buffer pitch (scalar frag loads)
#define WP    136    // W-buffer pitch ([c][k'] layout; LDS.64 conflict-free)
#define NREL  9261   // 21^3 possible rel vectors
#define NRELP 9344   // padded to 73*128
#define FPTS  16     // points per fused block

// ---------------- device scratch ------------------------------------------------
__device__ int   g_idx[TOT * KNN];
__device__ float g_t  [TOT * HD];
__device__ float g_qg [TOT * HD];     // BN(t) @ (Wphi@Wg1) + bg1
__device__ float g_kg [TOT * HD];     // BN(t) @ (Wpsi@Wg1)
__device__ float g_v  [TOT * HD];
__device__ float g_agg[TOT * HD];
__device__ float g_part[128 * 2 * HD];
__device__ float g_stats[2 * HD];
__device__ float g_wtf[6 * HD * HD];  // tf32 [c][k']: Wg2,WqG,WkG,Walpha,Wd2,WdG
__device__ float g_bdG[HD];           // bd2 @ Wg1
__device__ float g_dtab [NRELP * HD]; // delta(rel) table
__device__ float g_dgtab[NRELP * HD]; // delta(rel)@Wg1 table (+bdG)
__device__ unsigned int g_tick1;
__device__ unsigned int g_tick2;

__device__ __forceinline__ float to_tf32(float x) {
    unsigned int r;
    asm("cvt.rna.tf32.f32 %0, %1;" : "=r"(r) : "f"(x));
    return __uint_as_float(r);
}
__device__ __forceinline__ int permk(int k) {          // per-8 k permutation
    return (k & ~7) | ((k & 3) << 1) | ((k >> 2) & 1); // k=t -> 2t ; k=t+4 -> 2t+1
}

__device__ __forceinline__ void cp16(void* dst_smem, const void* src) {
    unsigned int d = (unsigned int)__cvta_generic_to_shared(dst_smem);
    asm volatile("cp.async.cg.shared.global [%0], [%1], 16;\n" :: "r"(d), "l"(src));
}
__device__ __forceinline__ void cp_commit() {
    asm volatile("cp.async.commit_group;\n");
}
template <int N>
__device__ __forceinline__ void cp_wait() {
    asm volatile("cp.async.wait_group %0;\n" :: "n"(N));
}

// ============ prep: composites + all tf32 [c][k'] conversions in ONE launch ======
// blocks 0..2 : C = {Wphi,Wpsi,Wd2}@Wg1 -> tf32 [c][k'] slots {1,2,5}
// block  3    : g_bdG = bd2@Wg1
// blocks 4..51: direct conversion Wg2->slot0, Walpha->slot3, Wd2->slot4
__global__ __launch_bounds__(256) void prep_kernel(const float* __restrict__ Wphi,
                                                   const float* __restrict__ Wpsi,
                                                   const float* __restrict__ Wd2,
                                                   const float* __restrict__ Wg1,
                                                   const float* __restrict__ bd2,
                                                   const float* __restrict__ Wg2,
                                                   const float* __restrict__ Walpha) {
    int m = blockIdx.x;
    int tid = threadIdx.x;
    if (m >= 4) {
        // direct conversions: 3 matrices x 4096 float4s, 48 blocks x 256 threads
        int e = (m - 4) * 256 + tid;          // 0..12287
        const float* srcs[3] = {Wg2, Walpha, Wd2};
        const int slots[3] = {0, 3, 4};
        int mm = e / 4096;
        int idx = e & 4095;
        int k = idx >> 5, c = (idx & 31) * 4;
        float4 v = *(const float4*)&srcs[mm][k * 128 + c];
        int kp = permk(k);
        float* dst = g_wtf + slots[mm] * 16384;
        dst[(c + 0) * 128 + kp] = to_tf32(v.x);
        dst[(c + 1) * 128 + kp] = to_tf32(v.y);
        dst[(c + 2) * 128 + kp] = to_tf32(v.z);
        dst[(c + 3) * 128 + kp] = to_tf32(v.w);
        return;
    }
    if (m == 3) {
        if (tid < 128) {
            float s = 0.f;
            for (int k = 0; k < 128; k++)
                s += bd2[k] * Wg1[k * 128 + tid];
            g_bdG[tid] = s;
        }
        return;
    }
    // composite GEMM: C[k][c] = A[k][:]@Wg1[:][c]; write tf32 transposed
    const float* A = (m == 0) ? Wphi : (m == 1) ? Wpsi : Wd2;
    const int slot = (m == 0) ? 1 : (m == 1) ? 2 : 5;
    float* dst = g_wtf + slot * 16384;
    __shared__ float As[16][128];
    __shared__ float Bs[16][128];
    int ty = tid >> 4, tx = tid & 15;
    float acc[8][8] = {};
    for (int kt = 0; kt < 128; kt += 16) {
        for (int e = tid; e < 2048; e += 256) {
            int r = e >> 4, k = e & 15;
            As[k][r] = A[r * 128 + kt + k];
        }
        for (int e = tid; e < 2048; e += 256) {
            int k = e >> 7, c = e & 127;
            Bs[k][c] = Wg1[(kt + k) * 128 + c];
        }
        __syncthreads();
        #pragma unroll
        for (int k = 0; k < 16; k++) {
            float av[8], bv[8];
            #pragma unroll
            for (int i = 0; i < 8; i++) av[i] = As[k][ty * 8 + i];
            #pragma unroll
            for (int j = 0; j < 8; j++) bv[j] = Bs[k][tx * 8 + j];
            #pragma unroll
            for (int i = 0; i < 8; i++)
                #pragma unroll
                for (int j = 0; j < 8; j++)
                    acc[i][j] += av[i] * bv[j];
        }
        __syncthreads();
    }
    // write tf32, transposed [c][k'] with per-8 k permutation (row r = k here)
    #pragma unroll
    for (int i = 0; i < 8; i++) {
        int r = ty * 8 + i;
        int rp = (r & ~7) | (((r & 3) << 1) | ((r >> 2) & 1));
        #pragma unroll
        for (int j = 0; j < 8; j++)
            dst[(tx * 8 + j) * 128 + rp] = to_tf32(acc[i][j]);
    }
}

// ============================ ball query =========================================
__global__ __launch_bounds__(128) void ball_kernel(const int* __restrict__ coords) {
    __shared__ int sP[NPTS];
    int b = (blockIdx.x * 128) / NPTS;
    int base = b * NPTS;
    for (int j = threadIdx.x; j < NPTS; j += 128) {
        int4 c = *(const int4*)&coords[(size_t)(base + j) * 4];
        sP[j] = c.y | (c.z << 8) | (c.w << 16);
    }
    __syncthreads();
    int qi = blockIdx.x * 128 + threadIdx.x;
    int me = sP[qi - base];
    int qx = me & 255, qy = (me >> 8) & 255, qz = me >> 16;
    int cnt = 0, first = 0;
    int* out = g_idx + (size_t)qi * KNN;
    #pragma unroll 8
    for (int j = 0; j < NPTS; j++) {
        int p = sP[j];
        int dx = qx - (p & 255);
        int dy = qy - ((p >> 8) & 255);
        int dz = qz - (p >> 16);
        int d2 = dx * dx + dy * dy + dz * dz;
        if (d2 <= 100) {
            int gj = base + j;
            out[cnt] = gj;
            if (cnt == 0) first = gj;
            cnt++;
            if (cnt == KNN) break;
        }
    }
    for (int k = cnt; k < KNN; k++) out[k] = first;
}

// ============================ tf32 mma GEMM core =================================
// warp tile 32x32; m16n8k8. A [M][AP] row-major tf32 (scalar frags);
// W [128][WP] [c][k'] (LDS.64 frags).
__device__ __forceinline__ void gemm_mma(const float* __restrict__ A,
                                         const float* __restrict__ W,
                                         float acc[2][4][4],
                                         int wr, int wc, int g, int t) {
    #pragma unroll
    for (int i = 0; i < 2; i++)
        #pragma unroll
        for (int j = 0; j < 4; j++)
            #pragma unroll
            for (int r = 0; r < 4; r++) acc[i][j][r] = 0.f;
    #pragma unroll 4
    for (int kk = 0; kk < 16; kk++) {
        const int k0 = kk * 8;
        unsigned int a[2][4];
        #pragma unroll
        for (int mi = 0; mi < 2; mi++) {
            const float* ap = A + (size_t)(wr * 32 + mi * 16 + g) * AP + k0 + t;
            a[mi][0] = __float_as_uint(ap[0]);
            a[mi][1] = __float_as_uint(ap[8 * AP]);
            a[mi][2] = __float_as_uint(ap[4]);
            a[mi][3] = __float_as_uint(ap[8 * AP + 4]);
        }
        #pragma unroll
        for (int ni = 0; ni < 4; ni++) {
            const float* bp = W + (size_t)(wc * 32 + ni * 8 + g) * WP + k0 + 2 * t;
            float2 bb = *(const float2*)bp;
            unsigned int b0 = __float_as_uint(bb.x);
            unsigned int b1 = __float_as_uint(bb.y);
            #pragma unroll
            for (int mi = 0; mi < 2; mi++) {
                asm volatile(
                    "mma.sync.aligned.m16n8k8.row.col.f32.tf32.tf32.f32 "
                    "{%0,%1,%2,%3}, {%4,%5,%6,%7}, {%8,%9}, {%0,%1,%2,%3};\n"
                    : "+f"(acc[mi][ni][0]), "+f"(acc[mi][ni][1]),
                      "+f"(acc[mi][ni][2]), "+f"(acc[mi][ni][3])
                    : "r"(a[mi][0]), "r"(a[mi][1]), "r"(a[mi][2]), "r"(a[mi][3]),
                      "r"(b0), "r"(b1));
            }
        }
    }
}

__device__ __forceinline__ void ldW_async(float* dstBase, const float* src, int tid,
                                          int nthreads) {
    for (int e = tid; e < 4096; e += nthreads) {
        int r = e >> 5, c = (e & 31) * 4;
        cp16(dstBase + r * WP + c, src + r * 128 + c);
    }
}

// ============== delta tables: dtab = relu(rel@Wd1+bd1)@Wd2+bd2, dgtab = .. @Wg1 ==
__global__ __launch_bounds__(512) void table_kernel(const float* __restrict__ Wd1,
                                                    const float* __restrict__ bd1,
                                                    const float* __restrict__ bd2) {
    extern __shared__ float sm[];
    float* BufA = sm;                    // [128][AP]
    float* W0   = BufA + 128 * AP;       // [128][WP]  Wd2
    float* W1   = W0 + 128 * WP;         // [128][WP]  WdG
    __shared__ float sWd1[384], sBd1[128];
    int tid = threadIdx.x;
    int row0 = blockIdx.x * 128;

    ldW_async(W0, g_wtf + 4 * 16384, tid, 512);  cp_commit();
    ldW_async(W1, g_wtf + 5 * 16384, tid, 512);  cp_commit();

    if (tid < 384) sWd1[tid] = Wd1[tid];
    if (tid < 128) sBd1[tid] = bd1[tid];
    __syncthreads();

    for (int e = tid; e < 128 * 128; e += 512) {
        int r = e >> 7, c = e & 127;
        int idx = row0 + r;
        if (idx > NREL - 1) idx = NREL - 1;
        float dx = (float)(idx % 21 - 10);
        float dy = (float)((idx / 21) % 21 - 10);
        float dz = (float)(idx / 441 - 10);
        float v = sBd1[c] + dx * sWd1[c] + dy * sWd1[128 + c] + dz * sWd1[256 + c];
        BufA[r * AP + c] = to_tf32(fmaxf(v, 0.f));
    }
    cp_wait<1>();
    __syncthreads();

    int wid = tid >> 5, lane = tid & 31;
    int wr = wid >> 2, wc = wid & 3;
    int g = lane >> 2, t = lane & 3;

    float acc[2][4][4];
    gemm_mma(BufA, W0, acc, wr, wc, g, t);    // delta
    #pragma unroll
    for (int mi = 0; mi < 2; mi++) {
        int r0 = row0 + wr * 32 + mi * 16 + g;
        #pragma unroll
        for (int ni = 0; ni < 4; ni++) {
            int c0 = wc * 32 + ni * 8 + 2 * t;
            float b0 = __ldg(&bd2[c0]), b1 = __ldg(&bd2[c0 + 1]);
            *(float2*)&g_dtab[(size_t)r0 * 128 + c0] =
                make_float2(acc[mi][ni][0] + b0, acc[mi][ni][1] + b1);
            *(float2*)&g_dtab[(size_t)(r0 + 8) * 128 + c0] =
                make_float2(acc[mi][ni][2] + b0, acc[mi][ni][3] + b1);
        }
    }
    cp_wait<0>();
    gemm_mma(BufA, W1, acc, wr, wc, g, t);    // delta @ Wg1 (+bdG)
    #pragma unroll
    for (int mi = 0; mi < 2; mi++) {
        int r0 = row0 + wr * 32 + mi * 16 + g;
        #pragma unroll
        for (int ni = 0; ni < 4; ni++) {
            int c0 = wc * 32 + ni * 8 + 2 * t;
            float b0 = g_bdG[c0], b1 = g_bdG[c0 + 1];
            *(float2*)&g_dgtab[(size_t)r0 * 128 + c0] =
                make_float2(acc[mi][ni][0] + b0, acc[mi][ni][1] + b1);
            *(float2*)&g_dgtab[(size_t)(r0 + 8) * 128 + c0] =
                make_float2(acc[mi][ni][2] + b0, acc[mi][ni][3] + b1);
        }
    }
}

// ================ t = x @ W_top + b_top, fused BN partials + finalize ===========
__global__ __launch_bounds__(256) void topproj_kernel(const float* __restrict__ x,
                                                      const float* __restrict__ W,
                                                      const float* __restrict__ bias) {
    __shared__ float As[16][128];
    __shared__ float Bs[16][128];
    __shared__ float redS[16][128];
    __shared__ float redSS[16][128];
    __shared__ double dS[2][128];
    __shared__ double dSS[2][128];
    __shared__ bool  sLast;
    int tid = threadIdx.x;
    int ty = tid >> 4, tx = tid & 15;
    int row0 = blockIdx.x * 128;
    float acc[8][8] = {};
    for (int kt = 0; kt < 64; kt += 16) {
        for (int e = tid; e < 512; e += 256) {
            int r = e >> 2, s = e & 3;
            float4 v = *(const float4*)&x[(size_t)(row0 + r) * 64 + kt + s * 4];
            As[s * 4 + 0][r] = v.x; As[s * 4 + 1][r] = v.y;
            As[s * 4 + 2][r] = v.z; As[s * 4 + 3][r] = v.w;
        }
        for (int e = tid; e < 512; e += 256) {
            int k = e >> 5, s = e & 31;
            *(float4*)&Bs[k][s * 4] = *(const float4*)&W[(size_t)(kt + k) * 128 + s * 4];
        }
        __syncthreads();
        #pragma unroll
        for (int k = 0; k < 16; k++) {
            float4 a0 = *(const float4*)&As[k][ty * 8];
            float4 a1 = *(const float4*)&As[k][ty * 8 + 4];
            float4 b0 = *(const float4*)&Bs[k][tx * 8];
            float4 b1 = *(const float4*)&Bs[k][tx * 8 + 4];
            float av[8] = {a0.x, a0.y, a0.z, a0.w, a1.x, a1.y, a1.z, a1.w};
            float bv[8] = {b0.x, b0.y, b0.z, b0.w, b1.x, b1.y, b1.z, b1.w};
            #pragma unroll
            for (int i = 0; i < 8; i++)
                #pragma unroll
                for (int j = 0; j < 8; j++)
                    acc[i][j] += av[i] * bv[j];
        }
        __syncthreads();
    }
    #pragma unroll
    for (int j = 0; j < 8; j++) {
        float b = __ldg(&bias[tx * 8 + j]);
        float s = 0.f, ss = 0.f;
        #pragma unroll
        for (int i = 0; i < 8; i++) {
            float v = acc[i][j] + b;
            g_t[(size_t)(row0 + ty * 8 + i) * 128 + tx * 8 + j] = v;
            s += v; ss += v * v;
        }
        redS[ty][tx * 8 + j] = s;
        redSS[ty][tx * 8 + j] = ss;
    }
    __syncthreads();
    if (tid < 128) {
        float s = 0.f, ss = 0.f;
        #pragma unroll
        for (int u = 0; u < 16; u++) { s += redS[u][tid]; ss += redSS[u][tid]; }
        g_part[blockIdx.x * 256 + tid]       = s;
        g_part[blockIdx.x * 256 + 128 + tid] = ss;
    }
    __threadfence();
    __syncthreads();
    if (tid == 0)
        sLast = (atomicAdd(&g_tick1, 1u) == gridDim.x - 1);
    __syncthreads();
    if (sLast) {
        int c = tid & 127, sub = tid >> 7;
        double s = 0.0, ss = 0.0;
        for (int b = sub; b < 128; b += 2) {
            s  += (double)g_part[b * 256 + c];
            ss += (double)g_part[b * 256 + 128 + c];
        }
        dS[sub][c] = s; dSS[sub][c] = ss;
        __syncthreads();
        if (tid < 128) {
            double S = dS[0][tid] + dS[1][tid];
            double SS = dSS[0][tid] + dSS[1][tid];
            double m = S / (double)TOT;
            double var = SS / (double)TOT - m * m;
            g_stats[tid]       = (float)m;
            g_stats[128 + tid] = rsqrtf((float)var + 1e-5f);
        }
        if (tid == 0) g_tick1 = 0u;
    }
}

// ============== qg,kg,v = normalize(t) @ {WqG,WkG,Walpha}; qg += bg1 =============
__global__ __launch_bounds__(512) void qkv_kernel(const float* __restrict__ g1v,
                                                  const float* __restrict__ be1,
                                                  const float* __restrict__ bg1) {
    extern __shared__ float sm[];
    float* BufA = sm;                    // [128][AP]
    float* W0   = BufA + 128 * AP;       // [128][WP]
    float* W1   = W0 + 128 * WP;         // [128][WP]
    __shared__ float sScale[128], sShift[128];
    int tid = threadIdx.x;

    ldW_async(W0, g_wtf + 1 * 16384, tid, 512);  cp_commit();  // WqG
    ldW_async(W1, g_wtf + 2 * 16384, tid, 512);  cp_commit();  // WkG

    if (tid < 128) {
        float m = g_stats[tid], is = g_stats[128 + tid];
        float sc = is * g1v[tid];
        sScale[tid] = sc;
        sShift[tid] = be1[tid] - m * sc;
    }
    __syncthreads();
    int row0 = blockIdx.x * 128;
    for (int e = tid; e < 4096; e += 512) {
        int r = e >> 5, s = (e & 31) * 4;
        float4 v = *(const float4*)&g_t[(size_t)(row0 + r) * 128 + s];
        float4 o;
        o.x = to_tf32(v.x * sScale[s] + sShift[s]);
        o.y = to_tf32(v.y * sScale[s + 1] + sShift[s + 1]);
        o.z = to_tf32(v.z * sScale[s + 2] + sShift[s + 2]);
        o.w = to_tf32(v.w * sScale[s + 3] + sShift[s + 3]);
        *(float4*)&BufA[r * AP + s] = o;
    }

    int wid = tid >> 5, lane = tid & 31;
    int wr = wid >> 2, wc = wid & 3;
    int g = lane >> 2, t = lane & 3;

    #pragma unroll 1
    for (int widx = 0; widx < 3; widx++) {
        float* out = (widx == 0) ? g_qg : (widx == 1) ? g_kg : g_v;
        const float* Wb = (widx == 1) ? W1 : W0;
        if (widx < 2) { cp_wait<1>(); } else { cp_wait<0>(); }
        __syncthreads();

        float acc[2][4][4];
        gemm_mma(BufA, Wb, acc, wr, wc, g, t);
        __syncthreads();

        if (widx == 0) {
            ldW_async(W0, g_wtf + 3 * 16384, tid, 512);
            cp_commit();
        }

        #pragma unroll
        for (int mi = 0; mi < 2; mi++) {
            int r0 = row0 + wr * 32 + mi * 16 + g;
            #pragma unroll
            for (int ni = 0; ni < 4; ni++) {
                int c0 = wc * 32 + ni * 8 + 2 * t;
                float b0 = 0.f, b1 = 0.f;
                if (widx == 0) { b0 = __ldg(&bg1[c0]); b1 = __ldg(&bg1[c0 + 1]); }
                *(float2*)&out[(size_t)r0 * 128 + c0] =
                    make_float2(acc[mi][ni][0] + b0, acc[mi][ni][1] + b1);
                *(float2*)&out[(size_t)(r0 + 8) * 128 + c0] =
                    make_float2(acc[mi][ni][2] + b0, acc[mi][ni][3] + b1);
            }
        }
    }
}

// ================== fused attention: 16 points/block, 1024 threads ===============
// h2 = relu(qg'_i - kg_j + dgtab[rel]); logits = h2@Wg2 + bg2;
// agg = softmax_K(logits) . (v_j + dtab[rel])
__global__ __launch_bounds__(1024) void fused_kernel(const int* __restrict__ coords,
                                                     const float* __restrict__ bg2) {
    extern __shared__ float sm[];
    float* BufA = sm;                      // [256][AP]
    float* W0   = BufA + 256 * AP;         // [128][WP]  Wg2
    float* sQg  = W0 + 128 * WP;           // [16][128]
    int*   sIdx = (int*)(sQg + FPTS * 128); // [256]
    int*   sCode = sIdx + 256;             // [256]

    int tid = threadIdx.x;
    int p0 = blockIdx.x * FPTS;
    int wid = tid >> 5, lane = tid & 31;
    int wr = wid >> 2, wc = wid & 3;     // wr 0..7, wc 0..3
    int g = lane >> 2, t = lane & 3;

    ldW_async(W0, g_wtf, tid, 1024);  cp_commit();   // Wg2

    if (tid < 256) {
        int j = g_idx[(size_t)p0 * KNN + tid];
        sIdx[tid] = j;
        int i = p0 + (tid >> 4);
        int4 ci = *(const int4*)&coords[(size_t)i * 4];
        int4 cj = *(const int4*)&coords[(size_t)j * 4];
        sCode[tid] = (ci.y - cj.y + 10) + 21 * (ci.z - cj.z + 10)
                   + 441 * (ci.w - cj.w + 10);
    }
    if (tid < 512) {
        int pp = tid >> 5, s = (tid & 31) * 4;
        *(float4*)&sQg[pp * 128 + s] = *(const float4*)&g_qg[(size_t)(p0 + pp) * 128 + s];
    }
    __syncthreads();

    // stage: BufA[r][c] = tf32(relu(qg' - kg + dg)), 256 rows
    for (int e = tid; e < 8192; e += 1024) {
        int r = e >> 5, s = (e & 31) * 4;
        int j = sIdx[r], code = sCode[r];
        int pl = r >> 4;
        float4 kg = *(const float4*)&g_kg[(size_t)j * 128 + s];
        float4 dg = *(const float4*)&g_dgtab[(size_t)code * 128 + s];
        float4 qv = *(const float4*)&sQg[pl * 128 + s];
        float4 o;
        o.x = to_tf32(fmaxf(qv.x - kg.x + dg.x, 0.f));
        o.y = to_tf32(fmaxf(qv.y - kg.y + dg.y, 0.f));
        o.z = to_tf32(fmaxf(qv.z - kg.z + dg.z, 0.f));
        o.w = to_tf32(fmaxf(qv.w - kg.w + dg.w, 0.f));
        *(float4*)&BufA[r * AP + s] = o;
    }
    cp_wait<0>();
    __syncthreads();

    // GEMM: logits = h2 @ Wg2 (+bg2 below); 256x128x128, 32 warps
    float acc2[2][4][4];
    gemm_mma(BufA, W0, acc2, wr, wc, g, t);

    // softmax over K + aggregate
    #pragma unroll
    for (int mi = 0; mi < 2; mi++) {
        int r0 = wr * 32 + mi * 16 + g;
        int r1 = r0 + 8;
        int pl = wr * 2 + mi;
        int gi0 = sIdx[r0], gi1 = sIdx[r1];
        int cd0 = sCode[r0], cd1 = sCode[r1];
        #pragma unroll
        for (int ni = 0; ni < 4; ni++) {
            int c0 = wc * 32 + ni * 8 + 2 * t;
            float b0 = __ldg(&bg2[c0]), b1 = __ldg(&bg2[c0 + 1]);
            float l00 = acc2[mi][ni][0] + b0, l01 = acc2[mi][ni][1] + b1;
            float l10 = acc2[mi][ni][2] + b0, l11 = acc2[mi][ni][3] + b1;
            float2 v0 = *(const float2*)&g_v[(size_t)gi0 * 128 + c0];
            float2 v1 = *(const float2*)&g_v[(size_t)gi1 * 128 + c0];
            float2 d0 = *(const float2*)&g_dtab[(size_t)cd0 * 128 + c0];
            float2 d1 = *(const float2*)&g_dtab[(size_t)cd1 * 128 + c0];
            float w00 = v0.x + d0.x, w01 = v0.y + d0.y;
            float w10 = v1.x + d1.x, w11 = v1.y + d1.y;

            float m0 = fmaxf(l00, l10);
            m0 = fmaxf(m0, __shfl_xor_sync(0xffffffffu, m0, 4));
            m0 = fmaxf(m0, __shfl_xor_sync(0xffffffffu, m0, 8));
            m0 = fmaxf(m0, __shfl_xor_sync(0xffffffffu, m0, 16));
            float m1 = fmaxf(l01, l11);
            m1 = fmaxf(m1, __shfl_xor_sync(0xffffffffu, m1, 4));
            m1 = fmaxf(m1, __shfl_xor_sync(0xffffffffu, m1, 8));
            m1 = fmaxf(m1, __shfl_xor_sync(0xffffffffu, m1, 16));

            float e00 = __expf(l00 - m0), e10 = __expf(l10 - m0);
            float e01 = __expf(l01 - m1), e11 = __expf(l11 - m1);
            float s0 = e00 + e10, s1 = e01 + e11;
            float a0 = e00 * w00 + e10 * w10;
            float a1 = e01 * w01 + e11 * w11;
            s0 += __shfl_xor_sync(0xffffffffu, s0, 4);
            s0 += __shfl_xor_sync(0xffffffffu, s0, 8);
            s0 += __shfl_xor_sync(0xffffffffu, s0, 16);
            s1 += __shfl_xor_sync(0xffffffffu, s1, 4);
            s1 += __shfl_xor_sync(0xffffffffu, s1, 8);
            s1 += __shfl_xor_sync(0xffffffffu, s1, 16);
            a0 += __shfl_xor_sync(0xffffffffu, a0, 4);
            a0 += __shfl_xor_sync(0xffffffffu, a0, 8);
            a0 += __shfl_xor_sync(0xffffffffu, a0, 16);
            a1 += __shfl_xor_sync(0xffffffffu, a1, 4);
            a1 += __shfl_xor_sync(0xffffffffu, a1, 8);
            a1 += __shfl_xor_sync(0xffffffffu, a1, 16);

            if (g == 0)
                *(float2*)&g_agg[(size_t)(p0 + pl) * 128 + c0] =
                    make_float2(a0 / s0, a1 / s1);
        }
    }
}

// ========== down-proj: out = agg @ W_down + b_down, fused BN partials ===========
__global__ __launch_bounds__(256) void down_kernel(const float* __restrict__ W,
                                                   const float* __restrict__ bias,
                                                   float* __restrict__ out) {
    __shared__ float As[16][128];
    __shared__ float Bs[16][64];
    __shared__ float redS[16][64];
    __shared__ float redSS[16][64];
    __shared__ double dS[4][64];
    __shared__ double dSS[4][64];
    __shared__ bool  sLast;
    int tid = threadIdx.x;
    int ty = tid >> 4, tx = tid & 15;
    int row0 = blockIdx.x * 128;
    float acc[8][4] = {};
    for (int kt = 0; kt < 128; kt += 16) {
        for (int e = tid; e < 512; e += 256) {
            int r = e >> 2, s = e & 3;
            float4 v = *(const float4*)&g_agg[(size_t)(row0 + r) * 128 + kt + s * 4];
            As[s * 4 + 0][r] = v.x; As[s * 4 + 1][r] = v.y;
            As[s * 4 + 2][r] = v.z; As[s * 4 + 3][r] = v.w;
        }
        if (tid < 256) {
            int k = tid >> 4, s = tid & 15;
            *(float4*)&Bs[k][s * 4] = *(const float4*)&W[(size_t)(kt + k) * 64 + s * 4];
        }
        __syncthreads();
        #pragma unroll
        for (int k = 0; k < 16; k++) {
            float4 a0 = *(const float4*)&As[k][ty * 8];
            float4 a1 = *(const float4*)&As[k][ty * 8 + 4];
            float4 b = *(const float4*)&Bs[k][tx * 4];
            float av[8] = {a0.x, a0.y, a0.z, a0.w, a1.x, a1.y, a1.z, a1.w};
            float bv[4] = {b.x, b.y, b.z, b.w};
            #pragma unroll
            for (int i = 0; i < 8; i++)
                #pragma unroll
                for (int j = 0; j < 4; j++)
                    acc[i][j] += av[i] * bv[j];
        }
        __syncthreads();
    }
    #pragma unroll
    for (int j = 0; j < 4; j++) {
        float b = __ldg(&bias[tx * 4 + j]);
        float s = 0.f, ss = 0.f;
        #pragma unroll
        for (int i = 0; i < 8; i++) {
            float v = acc[i][j] + b;
            out[(size_t)(row0 + ty * 8 + i) * 64 + tx * 4 + j] = v;
            s += v; ss += v * v;
        }
        redS[ty][tx * 4 + j] = s;
        redSS[ty][tx * 4 + j] = ss;
    }
    __syncthreads();
    if (tid < 64) {
        float s = 0.f, ss = 0.f;
        #pragma unroll
        for (int u = 0; u < 16; u++) { s += redS[u][tid]; ss += redSS[u][tid]; }
        g_part[blockIdx.x * 128 + tid]      = s;
        g_part[blockIdx.x * 128 + 64 + tid] = ss;
    }
    __threadfence();
    __syncthreads();
    if (tid == 0)
        sLast = (atomicAdd(&g_tick2, 1u) == gridDim.x - 1);
    __syncthreads();
    if (sLast) {
        int c = tid & 63, sub = tid >> 6;
        double s = 0.0, ss = 0.0;
        for (int b = sub; b < 128; b += 4) {
            s  += (double)g_part[b * 128 + c];
            ss += (double)g_part[b * 128 + 64 + c];
        }
        dS[sub][c] = s; dSS[sub][c] = ss;
        __syncthreads();
        if (tid < 64) {
            double S = dS[0][tid] + dS[1][tid] + dS[2][tid] + dS[3][tid];
            double SS = dSS[0][tid] + dSS[1][tid] + dSS[2][tid] + dSS[3][tid];
            double m = S / (double)TOT;
            double var = SS / (double)TOT - m * m;
            g_stats[tid]      = (float)m;
            g_stats[64 + tid] = rsqrtf((float)var + 1e-5f);
        }
        if (tid == 0) g_tick2 = 0u;
    }
}

// ============================ final BN + residual ================================
__global__ __launch_bounds__(256) void final_kernel(const float* __restrict__ x,
                                                    const float* __restrict__ g2,
                                                    const float* __restrict__ be2,
                                                    float* __restrict__ out) {
    int e = blockIdx.x * 256 + threadIdx.x;
    if (e < TOT * IND) {
        int c = e & 63;
        float m = g_stats[c], is = g_stats[IND + c];
        out[e] = (out[e] - m) * is * g2[c] + be2[c] + x[e];
    }
}

// ============================ launch =============================================
extern "C" void kernel_launch(void* const* d_in, const int* in_sizes, int n_in,
                              void* d_out, int out_size) {
    const int*   coords  = (const int*)  d_in[0];
    const float* x       = (const float*)d_in[1];
    const float* W_top   = (const float*)d_in[2];
    const float* b_top   = (const float*)d_in[3];
    const float* g1      = (const float*)d_in[4];
    const float* be1     = (const float*)d_in[5];
    const float* W_phi   = (const float*)d_in[6];
    const float* W_psi   = (const float*)d_in[7];
    const float* W_alpha = (const float*)d_in[8];
    const float* Wd1     = (const float*)d_in[9];
    const float* bd1     = (const float*)d_in[10];
    const float* Wd2     = (const float*)d_in[11];
    const float* bd2     = (const float*)d_in[12];
    const float* Wg1     = (const float*)d_in[13];
    const float* bg1     = (const float*)d_in[14];
    const float* Wg2     = (const float*)d_in[15];
    const float* bg2     = (const float*)d_in[16];
    const float* W_down  = (const float*)d_in[17];
    const float* b_down  = (const float*)d_in[18];
    const float* g2      = (const float*)d_in[19];
    const float* be2     = (const float*)d_in[20];
    float* out = (float*)d_out;

    const size_t SMEM_F = (size_t)(256 * AP + 128 * WP + FPTS * 128
                                   + 256 + 256) * 4;
    const size_t SMEM_Q = (size_t)(128 * AP + 2 * 128 * WP) * 4;
    cudaFuncSetAttribute(fused_kernel, cudaFuncAttributeMaxDynamicSharedMemorySize,
                         (int)SMEM_F);
    cudaFuncSetAttribute(qkv_kernel, cudaFuncAttributeMaxDynamicSharedMemorySize,
                         (int)SMEM_Q);
    cudaFuncSetAttribute(table_kernel, cudaFuncAttributeMaxDynamicSharedMemorySize,
                         (int)SMEM_Q);

    prep_kernel<<<52, 256>>>(W_phi, W_psi, Wd2, Wg1, bd2, Wg2, W_alpha);
    ball_kernel<<<TOT / 128, 128>>>(coords);
    table_kernel<<<NRELP / 128, 512, SMEM_Q>>>(Wd1, bd1, bd2);
    topproj_kernel<<<TOT / 128, 256>>>(x, W_top, b_top);
    qkv_kernel<<<TOT / 128, 512, SMEM_Q>>>(g1, be1, bg1);
    fused_kernel<<<TOT / FPTS, 1024, SMEM_F>>>(coords, bg2);
    down_kernel<<<TOT / 128, 256>>>(W_down, b_down, out);
    final_kernel<<<(TOT * IND + 255) / 256, 256>>>(x, g2, be2, out);
}

// round 16
// speedup vs baseline: 1.3585x; 1.0240x over previous
#include <cuda_runtime.h>
#include <cuda_bf16.h>
#include <cstdint>
#include <math.h>

#define TOT   16384
#define NPTS  4096
#define KNN   16
#define HD    128
#define IND   64
#define AP    132    // A-buffer pitch (scalar frag loads)
#define WP    136    // W-buffer pitch ([c][k'] layout; LDS.64 conflict-free)
#define WPT   72     // W-buffer pitch for K=64 weights
#define NREL  9261   // 21^3 possible rel vectors
#define NRELP 9344   // padded to 73*128
#define FPTS  16     // points per fused block

// ---------------- device scratch ------------------------------------------------
__device__ int   g_idx[TOT * KNN];
__device__ float g_t  [TOT * HD];
__device__ float g_qg [TOT * HD];     // BN(t) @ (Wphi@Wg1) + bg1
__device__ float g_kg [TOT * HD];     // BN(t) @ (Wpsi@Wg1)
__device__ float g_v  [TOT * HD];
__device__ float g_agg[TOT * HD];
__device__ float g_part[128 * 2 * HD];
__device__ float g_stats[2 * HD];
__device__ float g_wtf[6 * HD * HD];  // tf32 [c][k']: Wg2,WqG,WkG,Walpha,Wd2,WdG
__device__ float g_wth[HD * 64];      // W_top hi, tf32 [c][k']
__device__ float g_wtl[HD * 64];      // W_top lo, tf32 [c][k']
__device__ float g_bdG[HD];           // bd2 @ Wg1
__device__ float g_dtab [NRELP * HD]; // delta(rel) table
__device__ float g_dgtab[NRELP * HD]; // delta(rel)@Wg1 table (+bdG)
__device__ unsigned int g_tick1;
__device__ unsigned int g_tick2;

__device__ __forceinline__ float to_tf32(float x) {
    unsigned int r;
    asm("cvt.rna.tf32.f32 %0, %1;" : "=r"(r) : "f"(x));
    return __uint_as_float(r);
}
__device__ __forceinline__ int permk(int k) {          // per-8 k permutation
    return (k & ~7) | ((k & 3) << 1) | ((k >> 2) & 1); // k=t -> 2t ; k=t+4 -> 2t+1
}

__device__ __forceinline__ void cp16(void* dst_smem, const void* src) {
    unsigned int d = (unsigned int)__cvta_generic_to_shared(dst_smem);
    asm volatile("cp.async.cg.shared.global [%0], [%1], 16;\n" :: "r"(d), "l"(src));
}
__device__ __forceinline__ void cp_commit() {
    asm volatile("cp.async.commit_group;\n");
}
template <int N>
__device__ __forceinline__ void cp_wait() {
    asm volatile("cp.async.wait_group %0;\n" :: "n"(N));
}

// ============ prep: composites + tf32 conversions (one launch) ===================
// blocks 0..2 : C = {Wphi,Wpsi,Wd2}@Wg1 -> tf32 [c][k'] slots {1,2,5}
// block  3    : g_bdG = bd2@Wg1
// blocks 4..51: direct conversion Wg2->slot0, Walpha->slot3, Wd2->slot4
// blocks 52..59: W_top hi/lo split -> g_wth/g_wtl [c][k']
__global__ __launch_bounds__(256) void prep_kernel(const float* __restrict__ Wphi,
                                                   const float* __restrict__ Wpsi,
                                                   const float* __restrict__ Wd2,
                                                   const float* __restrict__ Wg1,
                                                   const float* __restrict__ bd2,
                                                   const float* __restrict__ Wg2,
                                                   const float* __restrict__ Walpha,
                                                   const float* __restrict__ Wtop) {
    int m = blockIdx.x;
    int tid = threadIdx.x;
    if (m >= 52) {
        // W_top split: 64x128 source, 2048 float4s over 8 blocks x 256 threads
        int e = (m - 52) * 256 + tid;          // 0..2047
        int k = e >> 5, c = (e & 31) * 4;
        float4 v = *(const float4*)&Wtop[k * 128 + c];
        int kp = permk(k);
        float h0 = to_tf32(v.x), h1 = to_tf32(v.y);
        float h2 = to_tf32(v.z), h3 = to_tf32(v.w);
        g_wth[(c + 0) * 64 + kp] = h0;
        g_wth[(c + 1) * 64 + kp] = h1;
        g_wth[(c + 2) * 64 + kp] = h2;
        g_wth[(c + 3) * 64 + kp] = h3;
        g_wtl[(c + 0) * 64 + kp] = to_tf32(v.x - h0);
        g_wtl[(c + 1) * 64 + kp] = to_tf32(v.y - h1);
        g_wtl[(c + 2) * 64 + kp] = to_tf32(v.z - h2);
        g_wtl[(c + 3) * 64 + kp] = to_tf32(v.w - h3);
        return;
    }
    if (m >= 4) {
        int e = (m - 4) * 256 + tid;          // 0..12287
        const float* srcs[3] = {Wg2, Walpha, Wd2};
        const int slots[3] = {0, 3, 4};
        int mm = e / 4096;
        int idx = e & 4095;
        int k = idx >> 5, c = (idx & 31) * 4;
        float4 v = *(const float4*)&srcs[mm][k * 128 + c];
        int kp = permk(k);
        float* dst = g_wtf + slots[mm] * 16384;
        dst[(c + 0) * 128 + kp] = to_tf32(v.x);
        dst[(c + 1) * 128 + kp] = to_tf32(v.y);
        dst[(c + 2) * 128 + kp] = to_tf32(v.z);
        dst[(c + 3) * 128 + kp] = to_tf32(v.w);
        return;
    }
    if (m == 3) {
        if (tid < 128) {
            float s = 0.f;
            for (int k = 0; k < 128; k++)
                s += bd2[k] * Wg1[k * 128 + tid];
            g_bdG[tid] = s;
        }
        return;
    }
    const float* A = (m == 0) ? Wphi : (m == 1) ? Wpsi : Wd2;
    const int slot = (m == 0) ? 1 : (m == 1) ? 2 : 5;
    float* dst = g_wtf + slot * 16384;
    __shared__ float As[16][128];
    __shared__ float Bs[16][128];
    int ty = tid >> 4, tx = tid & 15;
    float acc[8][8] = {};
    for (int kt = 0; kt < 128; kt += 16) {
        for (int e = tid; e < 2048; e += 256) {
            int r = e >> 4, k = e & 15;
            As[k][r] = A[r * 128 + kt + k];
        }
        for (int e = tid; e < 2048; e += 256) {
            int k = e >> 7, c = e & 127;
            Bs[k][c] = Wg1[(kt + k) * 128 + c];
        }
        __syncthreads();
        #pragma unroll
        for (int k = 0; k < 16; k++) {
            float av[8], bv[8];
            #pragma unroll
            for (int i = 0; i < 8; i++) av[i] = As[k][ty * 8 + i];
            #pragma unroll
            for (int j = 0; j < 8; j++) bv[j] = Bs[k][tx * 8 + j];
            #pragma unroll
            for (int i = 0; i < 8; i++)
                #pragma unroll
                for (int j = 0; j < 8; j++)
                    acc[i][j] += av[i] * bv[j];
        }
        __syncthreads();
    }
    #pragma unroll
    for (int i = 0; i < 8; i++) {
        int r = ty * 8 + i;
        int rp = (r & ~7) | (((r & 3) << 1) | ((r >> 2) & 1));
        #pragma unroll
        for (int j = 0; j < 8; j++)
            dst[(tx * 8 + j) * 128 + rp] = to_tf32(acc[i][j]);
    }
}

// ============================ ball query =========================================
__global__ __launch_bounds__(128) void ball_kernel(const int* __restrict__ coords) {
    __shared__ int sP[NPTS];
    int b = (blockIdx.x * 128) / NPTS;
    int base = b * NPTS;
    for (int j = threadIdx.x; j < NPTS; j += 128) {
        int4 c = *(const int4*)&coords[(size_t)(base + j) * 4];
        sP[j] = c.y | (c.z << 8) | (c.w << 16);
    }
    __syncthreads();
    int qi = blockIdx.x * 128 + threadIdx.x;
    int me = sP[qi - base];
    int qx = me & 255, qy = (me >> 8) & 255, qz = me >> 16;
    int cnt = 0, first = 0;
    int* out = g_idx + (size_t)qi * KNN;
    #pragma unroll 8
    for (int j = 0; j < NPTS; j++) {
        int p = sP[j];
        int dx = qx - (p & 255);
        int dy = qy - ((p >> 8) & 255);
        int dz = qz - (p >> 16);
        int d2 = dx * dx + dy * dy + dz * dz;
        if (d2 <= 100) {
            int gj = base + j;
            out[cnt] = gj;
            if (cnt == 0) first = gj;
            cnt++;
            if (cnt == KNN) break;
        }
    }
    for (int k = cnt; k < KNN; k++) out[k] = first;
}

// ============================ tf32 mma GEMM cores ================================
// warp tile 32x32; m16n8k8. A row-major tf32 (scalar frags); W [c][k'] LDS.64.
__device__ __forceinline__ void gemm_mma(const float* __restrict__ A,
                                         const float* __restrict__ W,
                                         float acc[2][4][4],
                                         int wr, int wc, int g, int t) {
    #pragma unroll
    for (int i = 0; i < 2; i++)
        #pragma unroll
        for (int j = 0; j < 4; j++)
            #pragma unroll
            for (int r = 0; r < 4; r++) acc[i][j][r] = 0.f;
    #pragma unroll 4
    for (int kk = 0; kk < 16; kk++) {
        const int k0 = kk * 8;
        unsigned int a[2][4];
        #pragma unroll
        for (int mi = 0; mi < 2; mi++) {
            const float* ap = A + (size_t)(wr * 32 + mi * 16 + g) * AP + k0 + t;
            a[mi][0] = __float_as_uint(ap[0]);
            a[mi][1] = __float_as_uint(ap[8 * AP]);
            a[mi][2] = __float_as_uint(ap[4]);
            a[mi][3] = __float_as_uint(ap[8 * AP + 4]);
        }
        #pragma unroll
        for (int ni = 0; ni < 4; ni++) {
            const float* bp = W + (size_t)(wc * 32 + ni * 8 + g) * WP + k0 + 2 * t;
            float2 bb = *(const float2*)bp;
            unsigned int b0 = __float_as_uint(bb.x);
            unsigned int b1 = __float_as_uint(bb.y);
            #pragma unroll
            for (int mi = 0; mi < 2; mi++) {
                asm volatile(
                    "mma.sync.aligned.m16n8k8.row.col.f32.tf32.tf32.f32 "
                    "{%0,%1,%2,%3}, {%4,%5,%6,%7}, {%8,%9}, {%0,%1,%2,%3};\n"
                    : "+f"(acc[mi][ni][0]), "+f"(acc[mi][ni][1]),
                      "+f"(acc[mi][ni][2]), "+f"(acc[mi][ni][3])
                    : "r"(a[mi][0]), "r"(a[mi][1]), "r"(a[mi][2]), "r"(a[mi][3]),
                      "r"(b0), "r"(b1));
            }
        }
    }
}

// 8-kstep accumulating variant with W pitch WPT (K=64 weights)
__device__ __forceinline__ void gemm_mma8(const float* __restrict__ A,
                                          const float* __restrict__ W,
                                          float acc[2][4][4],
                                          int wr, int wc, int g, int t) {
    #pragma unroll
    for (int kk = 0; kk < 8; kk++) {
        const int k0 = kk * 8;
        unsigned int a[2][4];
        #pragma unroll
        for (int mi = 0; mi < 2; mi++) {
            const float* ap = A + (size_t)(wr * 32 + mi * 16 + g) * AP + k0 + t;
            a[mi][0] = __float_as_uint(ap[0]);
            a[mi][1] = __float_as_uint(ap[8 * AP]);
            a[mi][2] = __float_as_uint(ap[4]);
            a[mi][3] = __float_as_uint(ap[8 * AP + 4]);
        }
        #pragma unroll
        for (int ni = 0; ni < 4; ni++) {
            const float* bp = W + (size_t)(wc * 32 + ni * 8 + g) * WPT + k0 + 2 * t;
            float2 bb = *(const float2*)bp;
            unsigned int b0 = __float_as_uint(bb.x);
            unsigned int b1 = __float_as_uint(bb.y);
            #pragma unroll
            for (int mi = 0; mi < 2; mi++) {
                asm volatile(
                    "mma.sync.aligned.m16n8k8.row.col.f32.tf32.tf32.f32 "
                    "{%0,%1,%2,%3}, {%4,%5,%6,%7}, {%8,%9}, {%0,%1,%2,%3};\n"
                    : "+f"(acc[mi][ni][0]), "+f"(acc[mi][ni][1]),
                      "+f"(acc[mi][ni][2]), "+f"(acc[mi][ni][3])
                    : "r"(a[mi][0]), "r"(a[mi][1]), "r"(a[mi][2]), "r"(a[mi][3]),
                      "r"(b0), "r"(b1));
            }
        }
    }
}

__device__ __forceinline__ void ldW_async(float* dstBase, const float* src, int tid,
                                          int nthreads) {
    for (int e = tid; e < 4096; e += nthreads) {
        int r = e >> 5, c = (e & 31) * 4;
        cp16(dstBase + r * WP + c, src + r * 128 + c);
    }
}
__device__ __forceinline__ void ldW64_async(float* dstBase, const float* src, int tid,
                                            int nthreads) {
    for (int e = tid; e < 2048; e += nthreads) {
        int r = e >> 4, c = (e & 15) * 4;
        cp16(dstBase + r * WPT + c, src + r * 64 + c);
    }
}

// ============== delta tables: dtab = relu(rel@Wd1+bd1)@Wd2+bd2, dgtab = .. @Wg1 ==
__global__ __launch_bounds__(512) void table_kernel(const float* __restrict__ Wd1,
                                                    const float* __restrict__ bd1,
                                                    const float* __restrict__ bd2) {
    extern __shared__ float sm[];
    float* BufA = sm;                    // [128][AP]
    float* W0   = BufA + 128 * AP;       // [128][WP]  Wd2
    float* W1   = W0 + 128 * WP;         // [128][WP]  WdG
    __shared__ float sWd1[384], sBd1[128];
    int tid = threadIdx.x;
    int row0 = blockIdx.x * 128;

    ldW_async(W0, g_wtf + 4 * 16384, tid, 512);  cp_commit();
    ldW_async(W1, g_wtf + 5 * 16384, tid, 512);  cp_commit();

    if (tid < 384) sWd1[tid] = Wd1[tid];
    if (tid < 128) sBd1[tid] = bd1[tid];
    __syncthreads();

    for (int e = tid; e < 128 * 128; e += 512) {
        int r = e >> 7, c = e & 127;
        int idx = row0 + r;
        if (idx > NREL - 1) idx = NREL - 1;
        float dx = (float)(idx % 21 - 10);
        float dy = (float)((idx / 21) % 21 - 10);
        float dz = (float)(idx / 441 - 10);
        float v = sBd1[c] + dx * sWd1[c] + dy * sWd1[128 + c] + dz * sWd1[256 + c];
        BufA[r * AP + c] = to_tf32(fmaxf(v, 0.f));
    }
    cp_wait<1>();
    __syncthreads();

    int wid = tid >> 5, lane = tid & 31;
    int wr = wid >> 2, wc = wid & 3;
    int g = lane >> 2, t = lane & 3;

    float acc[2][4][4];
    gemm_mma(BufA, W0, acc, wr, wc, g, t);    // delta
    #pragma unroll
    for (int mi = 0; mi < 2; mi++) {
        int r0 = row0 + wr * 32 + mi * 16 + g;
        #pragma unroll
        for (int ni = 0; ni < 4; ni++) {
            int c0 = wc * 32 + ni * 8 + 2 * t;
            float b0 = __ldg(&bd2[c0]), b1 = __ldg(&bd2[c0 + 1]);
            *(float2*)&g_dtab[(size_t)r0 * 128 + c0] =
                make_float2(acc[mi][ni][0] + b0, acc[mi][ni][1] + b1);
            *(float2*)&g_dtab[(size_t)(r0 + 8) * 128 + c0] =
                make_float2(acc[mi][ni][2] + b0, acc[mi][ni][3] + b1);
        }
    }
    cp_wait<0>();
    gemm_mma(BufA, W1, acc, wr, wc, g, t);    // delta @ Wg1 (+bdG)
    #pragma unroll
    for (int mi = 0; mi < 2; mi++) {
        int r0 = row0 + wr * 32 + mi * 16 + g;
        #pragma unroll
        for (int ni = 0; ni < 4; ni++) {
            int c0 = wc * 32 + ni * 8 + 2 * t;
            float b0 = g_bdG[c0], b1 = g_bdG[c0 + 1];
            *(float2*)&g_dgtab[(size_t)r0 * 128 + c0] =
                make_float2(acc[mi][ni][0] + b0, acc[mi][ni][1] + b1);
            *(float2*)&g_dgtab[(size_t)(r0 + 8) * 128 + c0] =
                make_float2(acc[mi][ni][2] + b0, acc[mi][ni][3] + b1);
        }
    }
}

// ================ t = x @ W_top + b_top (tf32 split, fp32-accurate) ==============
// + fused BN partials + last-block finalize
__global__ __launch_bounds__(512) void topproj_kernel(const float* __restrict__ x,
                                                      const float* __restrict__ bias) {
    extern __shared__ float sm[];
    float* BufA  = sm;                    // [128][AP]: cols 0..63 xh, 64..127 xl
    float* W0    = BufA + 128 * AP;       // [128][WPT] W_top hi
    float* W1    = W0 + 128 * WPT;        // [128][WPT] W_top lo
    float* redS  = W1 + 128 * WPT;        // [32][128]
    float* redSS = redS + 32 * 128;       // [32][128]
    __shared__ double dS[2][128], dSS[2][128];
    __shared__ bool sLast;

    int tid = threadIdx.x;
    int row0 = blockIdx.x * 128;

    ldW64_async(W0, g_wth, tid, 512);  cp_commit();
    ldW64_async(W1, g_wtl, tid, 512);  cp_commit();

    // stage A: xh / xl
    for (int e = tid; e < 2048; e += 512) {
        int r = e >> 4, s = (e & 15) * 4;
        float4 v = *(const float4*)&x[(size_t)(row0 + r) * 64 + s];
        float h0 = to_tf32(v.x), h1 = to_tf32(v.y);
        float h2 = to_tf32(v.z), h3 = to_tf32(v.w);
        float* bh = &BufA[r * AP + s];
        bh[0] = h0; bh[1] = h1; bh[2] = h2; bh[3] = h3;
        float* bl = bh + 64;
        bl[0] = to_tf32(v.x - h0); bl[1] = to_tf32(v.y - h1);
        bl[2] = to_tf32(v.z - h2); bl[3] = to_tf32(v.w - h3);
    }
    cp_wait<0>();
    __syncthreads();

    int wid = tid >> 5, lane = tid & 31;
    int wr = wid >> 2, wc = wid & 3;
    int g = lane >> 2, t = lane & 3;

    float acc[2][4][4];
    #pragma unroll
    for (int i = 0; i < 2; i++)
        #pragma unroll
        for (int j = 0; j < 4; j++)
            #pragma unroll
            for (int r = 0; r < 4; r++) acc[i][j][r] = 0.f;
    gemm_mma8(BufA, W0, acc, wr, wc, g, t);        // xh @ Wh
    gemm_mma8(BufA, W1, acc, wr, wc, g, t);        // xh @ Wl
    gemm_mma8(BufA + 64, W0, acc, wr, wc, g, t);   // xl @ Wh

    // epilogue: write t, per-thread column sums -> redS/redSS
    #pragma unroll
    for (int ni = 0; ni < 4; ni++) {
        int c0 = wc * 32 + ni * 8 + 2 * t;
        float b0 = __ldg(&bias[c0]), b1 = __ldg(&bias[c0 + 1]);
        float v00 = acc[0][ni][0] + b0, v01 = acc[0][ni][1] + b1;
        float v02 = acc[0][ni][2] + b0, v03 = acc[0][ni][3] + b1;
        float v10 = acc[1][ni][0] + b0, v11 = acc[1][ni][1] + b1;
        float v12 = acc[1][ni][2] + b0, v13 = acc[1][ni][3] + b1;
        int r0 = wr * 32 + g;
        *(float2*)&g_t[(size_t)(row0 + r0) * 128 + c0]      = make_float2(v00, v01);
        *(float2*)&g_t[(size_t)(row0 + r0 + 8) * 128 + c0]  = make_float2(v02, v03);
        *(float2*)&g_t[(size_t)(row0 + r0 + 16) * 128 + c0] = make_float2(v10, v11);
        *(float2*)&g_t[(size_t)(row0 + r0 + 24) * 128 + c0] = make_float2(v12, v13);
        int rr = wr * 8 + g;
        redS[rr * 128 + c0]      = v00 + v02 + v10 + v12;
        redS[rr * 128 + c0 + 1]  = v01 + v03 + v11 + v13;
        redSS[rr * 128 + c0]     = v00 * v00 + v02 * v02 + v10 * v10 + v12 * v12;
        redSS[rr * 128 + c0 + 1] = v01 * v01 + v03 * v03 + v11 * v11 + v13 * v13;
    }
    __syncthreads();
    if (tid < 128) {
        float s = 0.f, ss = 0.f;
        #pragma unroll
        for (int u = 0; u < 32; u++) { s += redS[u * 128 + tid]; ss += redSS[u * 128 + tid]; }
        g_part[blockIdx.x * 256 + tid]       = s;
        g_part[blockIdx.x * 256 + 128 + tid] = ss;
    }
    __threadfence();
    __syncthreads();
    if (tid == 0)
        sLast = (atomicAdd(&g_tick1, 1u) == gridDim.x - 1);
    __syncthreads();
    if (sLast) {
        if (tid < 256) {
            int c = tid & 127, sub = tid >> 7;
            double s = 0.0, ss = 0.0;
            for (int b = sub; b < 128; b += 2) {
                s  += (double)g_part[b * 256 + c];
                ss += (double)g_part[b * 256 + 128 + c];
            }
            dS[sub][c] = s; dSS[sub][c] = ss;
        }
        __syncthreads();
        if (tid < 128) {
            double S = dS[0][tid] + dS[1][tid];
            double SS = dSS[0][tid] + dSS[1][tid];
            double m = S / (double)TOT;
            double var = SS / (double)TOT - m * m;
            g_stats[tid]       = (float)m;
            g_stats[128 + tid] = rsqrtf((float)var + 1e-5f);
        }
        if (tid == 0) g_tick1 = 0u;
    }
}

// ============== qg,kg,v = normalize(t) @ {WqG,WkG,Walpha}; qg += bg1 =============
__global__ __launch_bounds__(512) void qkv_kernel(const float* __restrict__ g1v,
                                                  const float* __restrict__ be1,
                                                  const float* __restrict__ bg1) {
    extern __shared__ float sm[];
    float* BufA = sm;                    // [128][AP]
    float* W0   = BufA + 128 * AP;       // [128][WP]
    float* W1   = W0 + 128 * WP;         // [128][WP]
    __shared__ float sScale[128], sShift[128];
    int tid = threadIdx.x;

    ldW_async(W0, g_wtf + 1 * 16384, tid, 512);  cp_commit();  // WqG
    ldW_async(W1, g_wtf + 2 * 16384, tid, 512);  cp_commit();  // WkG

    if (tid < 128) {
        float m = g_stats[tid], is = g_stats[128 + tid];
        float sc = is * g1v[tid];
        sScale[tid] = sc;
        sShift[tid] = be1[tid] - m * sc;
    }
    __syncthreads();
    int row0 = blockIdx.x * 128;
    for (int e = tid; e < 4096; e += 512) {
        int r = e >> 5, s = (e & 31) * 4;
        float4 v = *(const float4*)&g_t[(size_t)(row0 + r) * 128 + s];
        float4 o;
        o.x = to_tf32(v.x * sScale[s] + sShift[s]);
        o.y = to_tf32(v.y * sScale[s + 1] + sShift[s + 1]);
        o.z = to_tf32(v.z * sScale[s + 2] + sShift[s + 2]);
        o.w = to_tf32(v.w * sScale[s + 3] + sShift[s + 3]);
        *(float4*)&BufA[r * AP + s] = o;
    }

    int wid = tid >> 5, lane = tid & 31;
    int wr = wid >> 2, wc = wid & 3;
    int g = lane >> 2, t = lane & 3;

    #pragma unroll 1
    for (int widx = 0; widx < 3; widx++) {
        float* out = (widx == 0) ? g_qg : (widx == 1) ? g_kg : g_v;
        const float* Wb = (widx == 1) ? W1 : W0;
        if (widx < 2) { cp_wait<1>(); } else { cp_wait<0>(); }
        __syncthreads();

        float acc[2][4][4];
        gemm_mma(BufA, Wb, acc, wr, wc, g, t);
        __syncthreads();

        if (widx == 0) {
            ldW_async(W0, g_wtf + 3 * 16384, tid, 512);
            cp_commit();
        }

        #pragma unroll
        for (int mi = 0; mi < 2; mi++) {
            int r0 = row0 + wr * 32 + mi * 16 + g;
            #pragma unroll
            for (int ni = 0; ni < 4; ni++) {
                int c0 = wc * 32 + ni * 8 + 2 * t;
                float b0 = 0.f, b1 = 0.f;
                if (widx == 0) { b0 = __ldg(&bg1[c0]); b1 = __ldg(&bg1[c0 + 1]); }
                *(float2*)&out[(size_t)r0 * 128 + c0] =
                    make_float2(acc[mi][ni][0] + b0, acc[mi][ni][1] + b1);
                *(float2*)&out[(size_t)(r0 + 8) * 128 + c0] =
                    make_float2(acc[mi][ni][2] + b0, acc[mi][ni][3] + b1);
            }
        }
    }
}

// ================== fused attention: 16 points/block, 1024 threads ===============
__global__ __launch_bounds__(1024) void fused_kernel(const int* __restrict__ coords,
                                                     const float* __restrict__ bg2) {
    extern __shared__ float sm[];
    float* BufA = sm;                      // [256][AP]
    float* W0   = BufA + 256 * AP;         // [128][WP]  Wg2
    float* sQg  = W0 + 128 * WP;           // [16][128]
    int*   sIdx = (int*)(sQg + FPTS * 128); // [256]
    int*   sCode = sIdx + 256;             // [256]

    int tid = threadIdx.x;
    int p0 = blockIdx.x * FPTS;
    int wid = tid >> 5, lane = tid & 31;
    int wr = wid >> 2, wc = wid & 3;
    int g = lane >> 2, t = lane & 3;

    ldW_async(W0, g_wtf, tid, 1024);  cp_commit();   // Wg2

    if (tid < 256) {
        int j = g_idx[(size_t)p0 * KNN + tid];
        sIdx[tid] = j;
        int i = p0 + (tid >> 4);
        int4 ci = *(const int4*)&coords[(size_t)i * 4];
        int4 cj = *(const int4*)&coords[(size_t)j * 4];
        sCode[tid] = (ci.y - cj.y + 10) + 21 * (ci.z - cj.z + 10)
                   + 441 * (ci.w - cj.w + 10);
    }
    if (tid < 512) {
        int pp = tid >> 5, s = (tid & 31) * 4;
        *(float4*)&sQg[pp * 128 + s] = *(const float4*)&g_qg[(size_t)(p0 + pp) * 128 + s];
    }
    __syncthreads();

    for (int e = tid; e < 8192; e += 1024) {
        int r = e >> 5, s = (e & 31) * 4;
        int j = sIdx[r], code = sCode[r];
        int pl = r >> 4;
        float4 kg = *(const float4*)&g_kg[(size_t)j * 128 + s];
        float4 dg = *(const float4*)&g_dgtab[(size_t)code * 128 + s];
        float4 qv = *(const float4*)&sQg[pl * 128 + s];
        float4 o;
        o.x = to_tf32(fmaxf(qv.x - kg.x + dg.x, 0.f));
        o.y = to_tf32(fmaxf(qv.y - kg.y + dg.y, 0.f));
        o.z = to_tf32(fmaxf(qv.z - kg.z + dg.z, 0.f));
        o.w = to_tf32(fmaxf(qv.w - kg.w + dg.w, 0.f));
        *(float4*)&BufA[r * AP + s] = o;
    }
    cp_wait<0>();
    __syncthreads();

    float acc2[2][4][4];
    gemm_mma(BufA, W0, acc2, wr, wc, g, t);

    #pragma unroll
    for (int mi = 0; mi < 2; mi++) {
        int r0 = wr * 32 + mi * 16 + g;
        int r1 = r0 + 8;
        int pl = wr * 2 + mi;
        int gi0 = sIdx[r0], gi1 = sIdx[r1];
        int cd0 = sCode[r0], cd1 = sCode[r1];
        #pragma unroll
        for (int ni = 0; ni < 4; ni++) {
            int c0 = wc * 32 + ni * 8 + 2 * t;
            float b0 = __ldg(&bg2[c0]), b1 = __ldg(&bg2[c0 + 1]);
            float l00 = acc2[mi][ni][0] + b0, l01 = acc2[mi][ni][1] + b1;
            float l10 = acc2[mi][ni][2] + b0, l11 = acc2[mi][ni][3] + b1;
            float2 v0 = *(const float2*)&g_v[(size_t)gi0 * 128 + c0];
            float2 v1 = *(const float2*)&g_v[(size_t)gi1 * 128 + c0];
            float2 d0 = *(const float2*)&g_dtab[(size_t)cd0 * 128 + c0];
            float2 d1 = *(const float2*)&g_dtab[(size_t)cd1 * 128 + c0];
            float w00 = v0.x + d0.x, w01 = v0.y + d0.y;
            float w10 = v1.x + d1.x, w11 = v1.y + d1.y;

            float m0 = fmaxf(l00, l10);
            m0 = fmaxf(m0, __shfl_xor_sync(0xffffffffu, m0, 4));
            m0 = fmaxf(m0, __shfl_xor_sync(0xffffffffu, m0, 8));
            m0 = fmaxf(m0, __shfl_xor_sync(0xffffffffu, m0, 16));
            float m1 = fmaxf(l01, l11);
            m1 = fmaxf(m1, __shfl_xor_sync(0xffffffffu, m1, 4));
            m1 = fmaxf(m1, __shfl_xor_sync(0xffffffffu, m1, 8));
            m1 = fmaxf(m1, __shfl_xor_sync(0xffffffffu, m1, 16));

            float e00 = __expf(l00 - m0), e10 = __expf(l10 - m0);
            float e01 = __expf(l01 - m1), e11 = __expf(l11 - m1);
            float s0 = e00 + e10, s1 = e01 + e11;
            float a0 = e00 * w00 + e10 * w10;
            float a1 = e01 * w01 + e11 * w11;
            s0 += __shfl_xor_sync(0xffffffffu, s0, 4);
            s0 += __shfl_xor_sync(0xffffffffu, s0, 8);
            s0 += __shfl_xor_sync(0xffffffffu, s0, 16);
            s1 += __shfl_xor_sync(0xffffffffu, s1, 4);
            s1 += __shfl_xor_sync(0xffffffffu, s1, 8);
            s1 += __shfl_xor_sync(0xffffffffu, s1, 16);
            a0 += __shfl_xor_sync(0xffffffffu, a0, 4);
            a0 += __shfl_xor_sync(0xffffffffu, a0, 8);
            a0 += __shfl_xor_sync(0xffffffffu, a0, 16);
            a1 += __shfl_xor_sync(0xffffffffu, a1, 4);
            a1 += __shfl_xor_sync(0xffffffffu, a1, 8);
            a1 += __shfl_xor_sync(0xffffffffu, a1, 16);

            if (g == 0)
                *(float2*)&g_agg[(size_t)(p0 + pl) * 128 + c0] =
                    make_float2(a0 / s0, a1 / s1);
        }
    }
}

// ========== down-proj: out = agg @ W_down + b_down, fused BN partials ===========
__global__ __launch_bounds__(256) void down_kernel(const float* __restrict__ W,
                                                   const float* __restrict__ bias,
                                                   float* __restrict__ out) {
    __shared__ float As[16][128];
    __shared__ float Bs[16][64];
    __shared__ float redS[16][64];
    __shared__ float redSS[16][64];
    __shared__ double dS[4][64];
    __shared__ double dSS[4][64];
    __shared__ bool  sLast;
    int tid = threadIdx.x;
    int ty = tid >> 4, tx = tid & 15;
    int row0 = blockIdx.x * 128;
    float acc[8][4] = {};
    for (int kt = 0; kt < 128; kt += 16) {
        for (int e = tid; e < 512; e += 256) {
            int r = e >> 2, s = e & 3;
            float4 v = *(const float4*)&g_agg[(size_t)(row0 + r) * 128 + kt + s * 4];
            As[s * 4 + 0][r] = v.x; As[s * 4 + 1][r] = v.y;
            As[s * 4 + 2][r] = v.z; As[s * 4 + 3][r] = v.w;
        }
        if (tid < 256) {
            int k = tid >> 4, s = tid & 15;
            *(float4*)&Bs[k][s * 4] = *(const float4*)&W[(size_t)(kt + k) * 64 + s * 4];
        }
        __syncthreads();
        #pragma unroll
        for (int k = 0; k < 16; k++) {
            float4 a0 = *(const float4*)&As[k][ty * 8];
            float4 a1 = *(const float4*)&As[k][ty * 8 + 4];
            float4 b = *(const float4*)&Bs[k][tx * 4];
            float av[8] = {a0.x, a0.y, a0.z, a0.w, a1.x, a1.y, a1.z, a1.w};
            float bv[4] = {b.x, b.y, b.z, b.w};
            #pragma unroll
            for (int i = 0; i < 8; i++)
                #pragma unroll
                for (int j = 0; j < 4; j++)
                    acc[i][j] += av[i] * bv[j];
        }
        __syncthreads();
    }
    #pragma unroll
    for (int j = 0; j < 4; j++) {
        float b = __ldg(&bias[tx * 4 + j]);
        float s = 0.f, ss = 0.f;
        #pragma unroll
        for (int i = 0; i < 8; i++) {
            float v = acc[i][j] + b;
            out[(size_t)(row0 + ty * 8 + i) * 64 + tx * 4 + j] = v;
            s += v; ss += v * v;
        }
        redS[ty][tx * 4 + j] = s;
        redSS[ty][tx * 4 + j] = ss;
    }
    __syncthreads();
    if (tid < 64) {
        float s = 0.f, ss = 0.f;
        #pragma unroll
        for (int u = 0; u < 16; u++) { s += redS[u][tid]; ss += redSS[u][tid]; }
        g_part[blockIdx.x * 128 + tid]      = s;
        g_part[blockIdx.x * 128 + 64 + tid] = ss;
    }
    __threadfence();
    __syncthreads();
    if (tid == 0)
        sLast = (atomicAdd(&g_tick2, 1u) == gridDim.x - 1);
    __syncthreads();
    if (sLast) {
        int c = tid & 63, sub = tid >> 6;
        double s = 0.0, ss = 0.0;
        for (int b = sub; b < 128; b += 4) {
            s  += (double)g_part[b * 128 + c];
            ss += (double)g_part[b * 128 + 64 + c];
        }
        dS[sub][c] = s; dSS[sub][c] = ss;
        __syncthreads();
        if (tid < 64) {
            double S = dS[0][tid] + dS[1][tid] + dS[2][tid] + dS[3][tid];
            double SS = dSS[0][tid] + dSS[1][tid] + dSS[2][tid] + dSS[3][tid];
            double m = S / (double)TOT;
            double var = SS / (double)TOT - m * m;
            g_stats[tid]      = (float)m;
            g_stats[64 + tid] = rsqrtf((float)var + 1e-5f);
        }
        if (tid == 0) g_tick2 = 0u;
    }
}

// ============================ final BN + residual ================================
__global__ __launch_bounds__(256) void final_kernel(const float* __restrict__ x,
                                                    const float* __restrict__ g2,
                                                    const float* __restrict__ be2,
                                                    float* __restrict__ out) {
    int e = blockIdx.x * 256 + threadIdx.x;
    if (e < TOT * IND) {
        int c = e & 63;
        float m = g_stats[c], is = g_stats[IND + c];
        out[e] = (out[e] - m) * is * g2[c] + be2[c] + x[e];
    }
}

// ============================ launch =============================================
extern "C" void kernel_launch(void* const* d_in, const int* in_sizes, int n_in,
                              void* d_out, int out_size) {
    const int*   coords  = (const int*)  d_in[0];
    const float* x       = (const float*)d_in[1];
    const float* W_top   = (const float*)d_in[2];
    const float* b_top   = (const float*)d_in[3];
    const float* g1      = (const float*)d_in[4];
    const float* be1     = (const float*)d_in[5];
    const float* W_phi   = (const float*)d_in[6];
    const float* W_psi   = (const float*)d_in[7];
    const float* W_alpha = (const float*)d_in[8];
    const float* Wd1     = (const float*)d_in[9];
    const float* bd1     = (const float*)d_in[10];
    const float* Wd2     = (const float*)d_in[11];
    const float* bd2     = (const float*)d_in[12];
    const float* Wg1     = (const float*)d_in[13];
    const float* bg1     = (const float*)d_in[14];
    const float* Wg2     = (const float*)d_in[15];
    const float* bg2     = (const float*)d_in[16];
    const float* W_down  = (const float*)d_in[17];
    const float* b_down  = (const float*)d_in[18];
    const float* g2      = (const float*)d_in[19];
    const float* be2     = (const float*)d_in[20];
    float* out = (float*)d_out;

    const size_t SMEM_F = (size_t)(256 * AP + 128 * WP + FPTS * 128
                                   + 256 + 256) * 4;
    const size_t SMEM_Q = (size_t)(128 * AP + 2 * 128 * WP) * 4;
    const size_t SMEM_T = (size_t)(128 * AP + 2 * 128 * WPT + 2 * 32 * 128) * 4;
    cudaFuncSetAttribute(fused_kernel, cudaFuncAttributeMaxDynamicSharedMemorySize,
                         (int)SMEM_F);
    cudaFuncSetAttribute(qkv_kernel, cudaFuncAttributeMaxDynamicSharedMemorySize,
                         (int)SMEM_Q);
    cudaFuncSetAttribute(table_kernel, cudaFuncAttributeMaxDynamicSharedMemorySize,
                         (int)SMEM_Q);
    cudaFuncSetAttribute(topproj_kernel, cudaFuncAttributeMaxDynamicSharedMemorySize,
                         (int)SMEM_T);

    prep_kernel<<<60, 256>>>(W_phi, W_psi, Wd2, Wg1, bd2, Wg2, W_alpha, W_top);
    ball_kernel<<<TOT / 128, 128>>>(coords);
    table_kernel<<<NRELP / 128, 512, SMEM_Q>>>(Wd1, bd1, bd2);
    topproj_kernel<<<TOT / 128, 512, SMEM_T>>>(x, b_top);
    qkv_kernel<<<TOT / 128, 512, SMEM_Q>>>(g1, be1, bg1);
    fused_kernel<<<TOT / FPTS, 1024, SMEM_F>>>(coords, bg2);
    down_kernel<<<TOT / 128, 256>>>(W_down, b_down, out);
    final_kernel<<<(TOT * IND + 255) / 256, 256>>>(x, g2, be2, out);
}